// round 9
// baseline (speedup 1.0000x reference)
#include <cuda_runtime.h>
#include <cuda_bf16.h>
#include <math.h>
#include <stdint.h>

#define B 512
#define S 400
#define V 50000
#define E 512
#define H 256
#define EMB 128
#define KX (E + EMB + H)
#define G4 (4*H)

#define OUT_COV    ((size_t)B*V)
#define OUT_HT     (OUT_COV  + (size_t)B*S)
#define OUT_CT     (OUT_HT   + (size_t)B*H)
#define OUT_ATTN   (OUT_CT   + (size_t)B*H)
#define OUT_LOSS   (OUT_ATTN + (size_t)B*S)

__device__ float g_ctxp[4][B*E];
__device__ float g_embed[B*EMB];
__device__ float g_bcat[G4];
__device__ float g_gates[B*G4];
__device__ float g_cwp[4*B];
__device__ float g_exw[B];
__device__ float g_pgen[B];
__device__ float g_wsapp[B*H];
__device__ float g_bias2[H];
__device__ float g_energy[B*S];
__device__ float g_covpart[B];
__device__ float g_rowmax[B];
__device__ float g_rowinv[B];

__device__ __nv_bfloat16 g_WcatH[G4*KX], g_WcatL[G4*KX];
__device__ __nv_bfloat16 g_xcatH[B*KX],  g_xcatL[B*KX];
__device__ __nv_bfloat16 g_awhH[H*E],    g_awhL[H*E];
__device__ __nv_bfloat16 g_awsH[H*H],    g_awsL[H*H];
__device__ __nv_bfloat16 g_vWH[(size_t)V*H], g_vWL[(size_t)V*H];
__device__ __nv_bfloat16 g_htH[B*H],     g_htL[B*H];

// ---------- helpers ----------
__device__ __forceinline__ uint32_t smem_u32(const void* p) {
    uint32_t a;
    asm("{ .reg .u64 t; cvta.to.shared.u64 t, %1; cvt.u32.u64 %0, t; }" : "=r"(a) : "l"(p));
    return a;
}
__device__ __forceinline__ void ldm_x4(uint32_t* r, uint32_t addr) {
    asm volatile("ldmatrix.sync.aligned.m8n8.x4.shared.b16 {%0,%1,%2,%3}, [%4];"
        : "=r"(r[0]), "=r"(r[1]), "=r"(r[2]), "=r"(r[3]) : "r"(addr));
}
__device__ __forceinline__ void mma16816(float* d, const uint32_t* a, const uint32_t* b) {
    asm volatile("mma.sync.aligned.m16n8k16.row.col.f32.bf16.bf16.f32 "
        "{%0,%1,%2,%3}, {%4,%5,%6,%7}, {%8,%9}, {%0,%1,%2,%3};"
        : "+f"(d[0]), "+f"(d[1]), "+f"(d[2]), "+f"(d[3])
        : "r"(a[0]), "r"(a[1]), "r"(a[2]), "r"(a[3]), "r"(b[0]), "r"(b[1]));
}
__device__ __forceinline__ void cpa(uint32_t dst, const void* src) {
    asm volatile("cp.async.cg.shared.global [%0], [%1], 16;" :: "r"(dst), "l"(src));
}
__device__ __forceinline__ void cpa_z(uint32_t dst, const void* src, int sz) {
    asm volatile("cp.async.cg.shared.global [%0], [%1], 16, %2;" :: "r"(dst), "l"(src), "r"(sz));
}
#define CP_COMMIT() asm volatile("cp.async.commit_group;" ::: "memory")
#define CP_WAIT1()  asm volatile("cp.async.wait_group 1;" ::: "memory")
#define CP_WAIT0()  asm volatile("cp.async.wait_group 0;" ::: "memory")

__device__ __forceinline__ void st_hilo(char* hiB, char* loB, int row, int k, float4 v) {
    int off = row*80 + k*2;
    __nv_bfloat16 h0 = __float2bfloat16(v.x), h1 = __float2bfloat16(v.y),
                  h2 = __float2bfloat16(v.z), h3 = __float2bfloat16(v.w);
    __nv_bfloat16 l0 = __float2bfloat16(v.x - __bfloat162float(h0)),
                  l1 = __float2bfloat16(v.y - __bfloat162float(h1)),
                  l2 = __float2bfloat16(v.z - __bfloat162float(h2)),
                  l3 = __float2bfloat16(v.w - __bfloat162float(h3));
    *(__nv_bfloat162*)(hiB + off)     = __halves2bfloat162(h0, h1);
    *(__nv_bfloat162*)(hiB + off + 4) = __halves2bfloat162(h2, h3);
    *(__nv_bfloat162*)(loB + off)     = __halves2bfloat162(l0, l1);
    *(__nv_bfloat162*)(loB + off + 4) = __halves2bfloat162(l2, l3);
}
__device__ __forceinline__ void split2(float v, __nv_bfloat16* hp, __nv_bfloat16* lp) {
    __nv_bfloat16 h = __float2bfloat16(v);
    *hp = h;
    *lp = __float2bfloat16(v - __bfloat162float(h));
}
// one 32-k step for a 32x64 warp tile: 3-term bf16
__device__ __forceinline__ void mma_step(float acc[2][8][4],
    uint32_t aHa, uint32_t aLa, uint32_t bHa, uint32_t bLa) {
    uint32_t aH[2][4], aL[2][4], bH[4][4], bL[4][4];
    #pragma unroll
    for (int mt = 0; mt < 2; mt++) { ldm_x4(aH[mt], aHa + mt*1280); ldm_x4(aL[mt], aLa + mt*1280); }
    #pragma unroll
    for (int np = 0; np < 4; np++) { ldm_x4(bH[np], bHa + np*1280); ldm_x4(bL[np], bLa + np*1280); }
    #pragma unroll
    for (int mt = 0; mt < 2; mt++)
        #pragma unroll
        for (int np = 0; np < 4; np++) {
            mma16816(acc[mt][2*np],   aH[mt], bH[np]);
            mma16816(acc[mt][2*np+1], aH[mt], bH[np]+2);
            mma16816(acc[mt][2*np],   aH[mt], bL[np]);
            mma16816(acc[mt][2*np+1], aH[mt], bL[np]+2);
            mma16816(acc[mt][2*np],   aL[mt], bH[np]);
            mma16816(acc[mt][2*np+1], aL[mt], bH[np]+2);
        }
}

__device__ __forceinline__ float sigmoidf_(float x) { return 1.f / (1.f + expf(-x)); }

__device__ __forceinline__ float blk_sum(float v, float* red) {
    int tid = threadIdx.x;
    #pragma unroll
    for (int o = 16; o; o >>= 1) v += __shfl_down_sync(0xffffffffu, v, o);
    if ((tid & 31) == 0) red[tid >> 5] = v;
    __syncthreads();
    float r;
    if (tid < 32) {
        int nw = (blockDim.x + 31) >> 5;
        r = (tid < nw) ? red[tid] : 0.f;
        #pragma unroll
        for (int o = 16; o; o >>= 1) r += __shfl_down_sync(0xffffffffu, r, o);
        if (tid == 0) red[0] = r;
    }
    __syncthreads();
    r = red[0];
    __syncthreads();
    return r;
}
__device__ __forceinline__ float blk_max(float v, float* red) {
    int tid = threadIdx.x;
    #pragma unroll
    for (int o = 16; o; o >>= 1) v = fmaxf(v, __shfl_down_sync(0xffffffffu, v, o));
    if ((tid & 31) == 0) red[tid >> 5] = v;
    __syncthreads();
    float r;
    if (tid < 32) {
        int nw = (blockDim.x + 31) >> 5;
        r = (tid < nw) ? red[tid] : -1e30f;
        #pragma unroll
        for (int o = 16; o; o >>= 1) r = fmaxf(r, __shfl_down_sync(0xffffffffu, r, o));
        if (tid == 0) red[0] = r;
    }
    __syncthreads();
    r = red[0];
    __syncthreads();
    return r;
}

// ---------- fp32 -> bf16 hi/lo converter ----------
__global__ void k_cvt(const float* __restrict__ src, __nv_bfloat16* __restrict__ hi,
                      __nv_bfloat16* __restrict__ lo, int n) {
    int idx = (blockIdx.x*blockDim.x + threadIdx.x) * 4;
    if (idx < n) {
        float4 v = *(const float4*)(src + idx);
        __nv_bfloat16 h0, h1, h2, h3, l0, l1, l2, l3;
        split2(v.x, &h0, &l0); split2(v.y, &h1, &l1);
        split2(v.z, &h2, &l2); split2(v.w, &h3, &l3);
        *(__nv_bfloat162*)(hi + idx)     = __halves2bfloat162(h0, h1);
        *(__nv_bfloat162*)(hi + idx + 2) = __halves2bfloat162(h2, h3);
        *(__nv_bfloat162*)(lo + idx)     = __halves2bfloat162(l0, l1);
        *(__nv_bfloat162*)(lo + idx + 2) = __halves2bfloat162(l2, l3);
    }
}

// ---------- context (S quarters), embed, p_gen partials ----------
__global__ void k_context(const float* __restrict__ attn, const float* __restrict__ enc_out,
                          const int* __restrict__ dec_input, const float* __restrict__ emb_table,
                          const float* __restrict__ wh, const float* __restrict__ wx) {
    int b = blockIdx.x, q = blockIdx.y, tid = threadIdx.x;
    __shared__ float sa[S/4];
    __shared__ float red[32];
    int s0 = q * (S/4);
    for (int s = tid; s < S/4; s += 256) sa[s] = attn[(size_t)b*S + s0 + s];
    __syncthreads();
    const float* eb = enc_out + ((size_t)b*S + s0)*E;
    float a0 = 0.f, a1 = 0.f;
    #pragma unroll 4
    for (int s = 0; s < S/4; s++) {
        float a = sa[s];
        a0 += a * eb[(size_t)s*E + tid];
        a1 += a * eb[(size_t)s*E + 256 + tid];
    }
    g_ctxp[q][b*E + tid]       = a0;
    g_ctxp[q][b*E + 256 + tid] = a1;
    float cw = blk_sum(a0*wh[tid] + a1*wh[256+tid], red);
    if (tid == 0) g_cwp[q*B + b] = cw;
    if (q == 0) {
        float ew = 0.f;
        if (tid < EMB) {
            float e = emb_table[(size_t)dec_input[b]*EMB + tid];
            g_embed[b*EMB + tid] = e;
            ew = e * wx[tid];
        }
        float exw = blk_sum(ew, red);
        if (tid == 0) g_exw[b] = exw;
    }
}

__global__ void k_packw(const float* __restrict__ W_ih, const float* __restrict__ W_hh,
                        const float* __restrict__ b_ih, const float* __restrict__ b_hh,
                        const float* __restrict__ aws_b, const float* __restrict__ awh_b) {
    int idx = blockIdx.x*blockDim.x + threadIdx.x;
    if (idx < G4*KX) {
        int n = idx / KX, k = idx % KX;
        float w = (k < E+EMB) ? W_ih[(size_t)n*(E+EMB) + k] : W_hh[(size_t)n*H + (k - (E+EMB))];
        split2(w, &g_WcatH[idx], &g_WcatL[idx]);
    }
    if (idx < G4) g_bcat[idx] = b_ih[idx] + b_hh[idx];
    if (idx < H)  g_bias2[idx] = aws_b[idx] + awh_b[idx];
}
__global__ void k_packx(const float* __restrict__ h0) {
    int idx = blockIdx.x*blockDim.x + threadIdx.x;
    if (idx < B*KX) {
        int b = idx / KX, k = idx % KX;
        float v;
        if (k < E)          v = g_ctxp[0][b*E+k] + g_ctxp[1][b*E+k] + g_ctxp[2][b*E+k] + g_ctxp[3][b*E+k];
        else if (k < E+EMB) v = g_embed[b*EMB + (k - E)];
        else                v = h0[b*H + (k - E - EMB)];
        split2(v, &g_xcatH[idx], &g_xcatL[idx]);
    }
}

// ---------- HMMA GEMM, cp.async double-buffered: tile 128x128, K-chunk 32 ----------
#define HG_STAGE 40960
#define HG_SMEM  81920
__global__ void __launch_bounds__(256) hgemm(
        const __nv_bfloat16* __restrict__ Ah, const __nv_bfloat16* __restrict__ Al,
        const __nv_bfloat16* __restrict__ Wh, const __nv_bfloat16* __restrict__ Wl,
        const float* __restrict__ bias, float* __restrict__ C, int N, int K) {
    extern __shared__ __align__(16) char sm[];
    uint32_t sb = smem_u32(sm);

    int tid = threadIdx.x, wid = tid >> 5, lane = tid & 31;
    int m0 = blockIdx.y * 128, n0 = blockIdx.x * 128;
    int wr = (wid & 3) * 32, wc = (wid >> 2) * 64;
    int lr = lane & 7, sect = lane >> 3;
    uint32_t aoff = (uint32_t)((wr + (sect & 1)*8 + lr)*80 + (sect >> 1)*16);
    uint32_t boff = (uint32_t)((wc + (sect >> 1)*8 + lr)*80 + (sect & 1)*16);

    int r = tid >> 1, kb = (tid & 1) * 16;
    uint32_t doff = (uint32_t)(r*80 + kb*2);
    const char* aHs = (const char*)(Ah + (size_t)(m0 + r)*K + kb);
    const char* aLs = (const char*)(Al + (size_t)(m0 + r)*K + kb);
    int n = n0 + r;
    int wsz = (n < N) ? 16 : 0;
    int nc = (n < N) ? n : 0;
    const char* wHs = (const char*)(Wh + (size_t)nc*K + kb);
    const char* wLs = (const char*)(Wl + (size_t)nc*K + kb);

    float acc[2][8][4];
    #pragma unroll
    for (int i = 0; i < 2; i++)
        #pragma unroll
        for (int j = 0; j < 8; j++)
            #pragma unroll
            for (int e = 0; e < 4; e++) acc[i][j][e] = 0.f;

    const int NC = K / 32;
    #pragma unroll
    for (int i = 0; i < 2; i++) {
        cpa(sb + doff + i*16,          aHs + i*16);
        cpa(sb + 10240 + doff + i*16,  aLs + i*16);
        cpa_z(sb + 20480 + doff + i*16, wHs + i*16, wsz);
        cpa_z(sb + 30720 + doff + i*16, wLs + i*16, wsz);
    }
    CP_COMMIT();

    for (int c = 0; c < NC; c++) {
        uint32_t st = sb + (uint32_t)((c & 1) * HG_STAGE);
        if (c + 1 < NC) {
            uint32_t st2 = sb + (uint32_t)(((c+1) & 1) * HG_STAGE);
            int ko = (c + 1) * 64;
            #pragma unroll
            for (int i = 0; i < 2; i++) {
                cpa(st2 + doff + i*16,          aHs + ko + i*16);
                cpa(st2 + 10240 + doff + i*16,  aLs + ko + i*16);
                cpa_z(st2 + 20480 + doff + i*16, wHs + ko + i*16, wsz);
                cpa_z(st2 + 30720 + doff + i*16, wLs + ko + i*16, wsz);
            }
            CP_COMMIT();
            CP_WAIT1();
        } else CP_WAIT0();
        __syncthreads();
        #pragma unroll
        for (int ks = 0; ks < 64; ks += 32)
            mma_step(acc, st + aoff + ks, st + 10240 + aoff + ks,
                          st + 20480 + boff + ks, st + 30720 + boff + ks);
        __syncthreads();
    }

    int gid = lane >> 2, t4 = lane & 3;
    #pragma unroll
    for (int mt = 0; mt < 2; mt++)
        #pragma unroll
        for (int eh = 0; eh < 2; eh++) {
            size_t row = (size_t)(m0 + wr + mt*16 + eh*8 + gid);
            #pragma unroll
            for (int nt = 0; nt < 8; nt++) {
                int col = n0 + wc + nt*8 + 2*t4;
                if (col + 1 < N) {
                    float2 v;
                    v.x = acc[mt][nt][eh*2+0] + bias[col];
                    v.y = acc[mt][nt][eh*2+1] + bias[col+1];
                    *(float2*)&C[row*(size_t)N + col] = v;
                } else if (col < N) {
                    C[row*(size_t)N + col] = acc[mt][nt][eh*2] + bias[col];
                }
            }
        }
}

// ---------- fused wh_app GEMM + energy: tile 128x256, 512 thr, 3-stage 1-sync ----------
// stage: WH 0, WL 20480, AH 40960, AL 51200 (61440/stage, 3 stages), floats at 184320
#define FK_STAGE 61440
#define FK_FLT   184320
#define FK_SMEM  (184320 + 8192)
__global__ void __launch_bounds__(512) fk_whenergy(const float* __restrict__ A,
        const __nv_bfloat16* __restrict__ Wh, const __nv_bfloat16* __restrict__ Wl,
        const float* __restrict__ coverage,
        const float* __restrict__ awc, const float* __restrict__ av) {
    extern __shared__ __align__(16) char sm[];
    uint32_t sb = smem_u32(sm);
    float* swsA = (float*)(sm + FK_FLT);
    float* swsB = (float*)(sm + FK_FLT + 1024);
    float* sawc = (float*)(sm + FK_FLT + 2048);
    float* sav  = (float*)(sm + FK_FLT + 3072);
    float* scov = (float*)(sm + FK_FLT + 4096);
    float* sred = (float*)(sm + FK_FLT + 4608);

    int tid = threadIdx.x, wid = tid >> 5, lane = tid & 31;
    int m0 = blockIdx.x * 128;
    int b0 = m0 / S;
    int b1 = (b0 + 1 < B) ? b0 + 1 : b0;
    int bswitch = (b0 + 1) * S - m0;
    int wr = (wid & 3) * 32, wc = (wid >> 2) * 64;
    int lr = lane & 7, sect = lane >> 3;
    uint32_t aoff = (uint32_t)((wr + (sect & 1)*8 + lr)*80 + (sect >> 1)*16);
    uint32_t boff = (uint32_t)((wc + (sect >> 1)*8 + lr)*80 + (sect & 1)*16);

    if (tid < 256) {
        swsA[tid] = g_wsapp[b0*H + tid];
        swsB[tid] = g_wsapp[b1*H + tid];
        sawc[tid] = awc[tid];
        sav[tid]  = av[tid];
    }
    if (tid < 128) scov[tid] = coverage[(size_t)m0 + tid];

    // W cp: row = tid>>1 (256 rows), (tid&1)*32B half of the 64B chunk row
    int wr2 = tid >> 1, wh2 = (tid & 1) * 32;
    const char* wHs = (const char*)(Wh + (size_t)wr2*E) + wh2;
    const char* wLs = (const char*)(Wl + (size_t)wr2*E) + wh2;
    uint32_t wdoff = (uint32_t)(wr2*80 + wh2);
    // A: row = tid>>2 (128 rows), 8 floats at (tid&3)*8
    int ar = tid >> 2, akb = (tid & 3) * 8;
    const float* aSrc = A + (size_t)(m0 + ar)*E + akb;

    float acc[2][8][4];
    #pragma unroll
    for (int i = 0; i < 2; i++)
        #pragma unroll
        for (int j = 0; j < 8; j++)
            #pragma unroll
            for (int e = 0; e < 4; e++) acc[i][j][e] = 0.f;

    // prologue: W[0] -> stage 0; A[0] -> regs
    #pragma unroll
    for (int i = 0; i < 2; i++) {
        cpa(sb + wdoff + i*16,         wHs + i*16);
        cpa(sb + 20480 + wdoff + i*16, wLs + i*16);
    }
    CP_COMMIT();
    float4 aN0 = *(const float4*)(aSrc);
    float4 aN1 = *(const float4*)(aSrc + 4);

    const int NC = E / 32;  // 16
    for (int c = 0; c < NC; c++) {
        int si = c % 3;
        uint32_t st = sb + (uint32_t)(si * FK_STAGE);
        char* stc = sm + si * FK_STAGE;
        // convert+store A[c] into stage c%3 (prev iter's readers are on stage (c-1)%3)
        st_hilo(stc + 40960, stc + 51200, ar, akb,     aN0);
        st_hilo(stc + 40960, stc + 51200, ar, akb + 4, aN1);
        if (c + 1 < NC) {
            uint32_t st2 = sb + (uint32_t)(((c+1) % 3) * FK_STAGE);
            int ko = (c + 1) * 64;  // bytes
            #pragma unroll
            for (int i = 0; i < 2; i++) {
                cpa(st2 + wdoff + i*16,         wHs + ko + i*16);
                cpa(st2 + 20480 + wdoff + i*16, wLs + ko + i*16);
            }
            CP_COMMIT();
            aN0 = *(const float4*)(aSrc + (c+1)*32);
            aN1 = *(const float4*)(aSrc + (c+1)*32 + 4);
            CP_WAIT1();
        } else CP_WAIT0();
        __syncthreads();   // single barrier per chunk
        #pragma unroll
        for (int ks = 0; ks < 64; ks += 32)
            mma_step(acc, st + 40960 + aoff + ks, st + 51200 + aoff + ks,
                          st + boff + ks,         st + 20480 + boff + ks);
    }
    __syncthreads();

    int gid = lane >> 2, t4 = lane & 3;
    int cg = wid >> 2;   // col group 0..3
    #pragma unroll
    for (int mt = 0; mt < 2; mt++)
        #pragma unroll
        for (int eh = 0; eh < 2; eh++) {
            int row = wr + mt*16 + eh*8 + gid;
            float c = scov[row];
            const float* sws = (row < bswitch) ? swsA : swsB;
            float p = 0.f;
            #pragma unroll
            for (int nt = 0; nt < 8; nt++)
                #pragma unroll
                for (int e2 = 0; e2 < 2; e2++) {
                    int h = wc + nt*8 + 2*t4 + e2;
                    float x = acc[mt][nt][eh*2 + e2] + sws[h] + c * sawc[h];
                    p += tanhf(x) * sav[h];
                }
            p += __shfl_xor_sync(0xffffffffu, p, 1);
            p += __shfl_xor_sync(0xffffffffu, p, 2);
            if (t4 == 0) sred[row*4 + cg] = p;
        }
    __syncthreads();
    if (tid < 128)
        g_energy[(size_t)m0 + tid] = sred[tid*4] + sred[tid*4+1] + sred[tid*4+2] + sred[tid*4+3];
}

// ---------- LSTM + p_gen ----------
__global__ void k_lstm(const float* __restrict__ c0, const float* __restrict__ ws,
                       float* __restrict__ out) {
    int b = blockIdx.x, h = threadIdx.x;
    __shared__ float red[32];
    const float* g = g_gates + (size_t)b*G4;
    float ig = sigmoidf_(g[h]);
    float fg = sigmoidf_(g[H + h]);
    float gg = tanhf(g[2*H + h]);
    float og = sigmoidf_(g[3*H + h]);
    float c  = fg * c0[b*H + h] + ig * gg;
    float ht = og * tanhf(c);
    out[OUT_CT + (size_t)b*H + h] = c;
    out[OUT_HT + (size_t)b*H + h] = ht;
    split2(ht, &g_htH[b*H + h], &g_htL[b*H + h]);
    float hw = blk_sum(ht * ws[h], red);
    if (h == 0)
        g_pgen[b] = sigmoidf_(g_cwp[b] + g_cwp[B+b] + g_cwp[2*B+b] + g_cwp[3*B+b] + hw + g_exw[b]);
}

// ---------- vocab softmax ----------
__global__ void k_rowstats(const float* __restrict__ out) {
    int b = blockIdx.x, tid = threadIdx.x;
    const float* row = out + (size_t)b*V;
    float m = -1e30f, s = 0.f;
    for (int v = tid; v < V; v += 1024) {
        float x = row[v];
        if (x > m) { s = s*expf(m - x) + 1.f; m = x; }
        else       { s += expf(x - m); }
    }
    __shared__ float sm_[1024], ss[1024];
    sm_[tid] = m; ss[tid] = s;
    __syncthreads();
    for (int off = 512; off; off >>= 1) {
        if (tid < off) {
            float m2 = sm_[tid+off], s2 = ss[tid+off];
            float M = fmaxf(sm_[tid], m2);
            ss[tid] = ss[tid]*expf(sm_[tid] - M) + s2*expf(m2 - M);
            sm_[tid] = M;
        }
        __syncthreads();
    }
    if (tid == 0) { g_rowmax[b] = sm_[0]; g_rowinv[b] = 1.f/ss[0]; }
}
// 2D grid: y = batch row, x covers V/4 float4s
__global__ void k_norm(float* __restrict__ out) {
    int b = blockIdx.y;
    int i = (blockIdx.x*blockDim.x + threadIdx.x) * 4;
    if (i < V) {
        float4* p = (float4*)(out + (size_t)b*V + i);
        float4 v = *p;
        float g = g_pgen[b], m = g_rowmax[b], inv = g_rowinv[b];
        v.x = g * expf(v.x - m) * inv;
        v.y = g * expf(v.y - m) * inv;
        v.z = g * expf(v.z - m) * inv;
        v.w = g * expf(v.w - m) * inv;
        *p = v;
    }
}

// ---------- attention softmax + coverage + loss ----------
__global__ void k_attn(const float* __restrict__ coverage, float* __restrict__ out) {
    int b = blockIdx.x, tid = threadIdx.x;
    __shared__ float red[32];
    float e = (tid < S) ? g_energy[b*S + tid] : -1e30f;
    float m = blk_max(e, red);
    float ex = (tid < S) ? expf(e - m) : 0.f;
    float sum = blk_sum(ex, red);
    float part = 0.f;
    if (tid < S) {
        float a = ex / sum;
        out[OUT_ATTN + (size_t)b*S + tid] = a;
        float c = coverage[(size_t)b*S + tid];
        out[OUT_COV + (size_t)b*S + tid] = c + a;
        part = fminf(a, c);
    }
    float ps = blk_sum(part, red);
    if (tid == 0) g_covpart[b] = ps;
}
__global__ void k_loss(float* __restrict__ out) {
    __shared__ float red[32];
    float s = blk_sum(g_covpart[threadIdx.x], red);
    if (threadIdx.x == 0) out[OUT_LOSS] = s;
}

// ---------- scatter (last-s-wins) ----------
__global__ void k_scatter(const int* __restrict__ enc_inputs, float* __restrict__ out) {
    int b = blockIdx.x, tid = threadIdx.x;
    __shared__ int   sidx[S];
    __shared__ float sat[S];
    if (tid < S) {
        sidx[tid] = enc_inputs[(size_t)b*S + tid];
        sat[tid]  = out[OUT_ATTN + (size_t)b*S + tid];
    }
    __syncthreads();
    if (tid < S) {
        int v = sidx[tid];
        bool win = true;
        for (int s2 = tid + 1; s2 < S; s2++)
            if (sidx[s2] == v) { win = false; break; }
        if (win) out[(size_t)b*V + v] += (1.f - g_pgen[b]) * sat[tid];
    }
}

// ---------- host ----------
extern "C" void kernel_launch(void* const* d_in, const int* in_sizes, int n_in,
                              void* d_out, int out_size) {
    const float* coverage   = (const float*)d_in[0];
    const float* enc_out    = (const float*)d_in[1];
    const float* h0         = (const float*)d_in[2];
    const float* c0         = (const float*)d_in[3];
    const float* attn       = (const float*)d_in[4];
    const int*   dec_input  = (const int*)d_in[5];
    const int*   enc_inputs = (const int*)d_in[6];
    const float* emb_table  = (const float*)d_in[7];
    const float* W_ih       = (const float*)d_in[8];
    const float* W_hh       = (const float*)d_in[9];
    const float* b_ih       = (const float*)d_in[10];
    const float* b_hh       = (const float*)d_in[11];
    const float* awh_W      = (const float*)d_in[12];
    const float* awh_b      = (const float*)d_in[13];
    const float* aws_W      = (const float*)d_in[14];
    const float* aws_b      = (const float*)d_in[15];
    const float* awc        = (const float*)d_in[16];
    const float* av         = (const float*)d_in[17];
    const float* wh         = (const float*)d_in[18];
    const float* ws         = (const float*)d_in[19];
    const float* wx         = (const float*)d_in[20];
    const float* v_W        = (const float*)d_in[21];
    const float* v_b        = (const float*)d_in[22];
    float* out = (float*)d_out;

    float *p_bcat, *p_gates, *p_wsapp, *p_bias2;
    __nv_bfloat16 *p_WcatH, *p_WcatL, *p_xcatH, *p_xcatL, *p_awhH, *p_awhL;
    __nv_bfloat16 *p_awsH, *p_awsL, *p_vWH, *p_vWL, *p_htH, *p_htL;
    cudaGetSymbolAddress((void**)&p_bcat,  g_bcat);
    cudaGetSymbolAddress((void**)&p_gates, g_gates);
    cudaGetSymbolAddress((void**)&p_wsapp, g_wsapp);
    cudaGetSymbolAddress((void**)&p_bias2, g_bias2);
    cudaGetSymbolAddress((void**)&p_WcatH, g_WcatH);
    cudaGetSymbolAddress((void**)&p_WcatL, g_WcatL);
    cudaGetSymbolAddress((void**)&p_xcatH, g_xcatH);
    cudaGetSymbolAddress((void**)&p_xcatL, g_xcatL);
    cudaGetSymbolAddress((void**)&p_awhH,  g_awhH);
    cudaGetSymbolAddress((void**)&p_awhL,  g_awhL);
    cudaGetSymbolAddress((void**)&p_awsH,  g_awsH);
    cudaGetSymbolAddress((void**)&p_awsL,  g_awsL);
    cudaGetSymbolAddress((void**)&p_vWH,   g_vWH);
    cudaGetSymbolAddress((void**)&p_vWL,   g_vWL);
    cudaGetSymbolAddress((void**)&p_htH,   g_htH);
    cudaGetSymbolAddress((void**)&p_htL,   g_htL);

    cudaFuncSetAttribute(fk_whenergy, cudaFuncAttributeMaxDynamicSharedMemorySize, FK_SMEM);
    cudaFuncSetAttribute(hgemm,       cudaFuncAttributeMaxDynamicSharedMemorySize, HG_SMEM);

    k_context<<<dim3(B, 4), 256>>>(attn, enc_out, dec_input, emb_table, wh, wx);
    k_packw<<<(G4*KX + 255)/256, 256>>>(W_ih, W_hh, b_ih, b_hh, aws_b, awh_b);
    k_cvt<<<(H*E/4 + 255)/256, 256>>>(awh_W, p_awhH, p_awhL, H*E);
    k_cvt<<<(H*H/4 + 255)/256, 256>>>(aws_W, p_awsH, p_awsL, H*H);
    k_cvt<<<(V*H/4 + 255)/256, 256>>>(v_W, p_vWH, p_vWL, V*H);
    k_packx<<<(B*KX + 255)/256, 256>>>(h0);
    hgemm<<<dim3(G4/128, B/128), 256, HG_SMEM>>>(p_xcatH, p_xcatL, p_WcatH, p_WcatL, p_bcat, p_gates, G4, KX);
    k_lstm<<<B, 256>>>(c0, ws, out);
    hgemm<<<dim3(H/128, B/128), 256, HG_SMEM>>>(p_htH, p_htL, p_awsH, p_awsL, p_bias2, p_wsapp, H, H);
    fk_whenergy<<<(B*S)/128, 512, FK_SMEM>>>(enc_out, p_awhH, p_awhL, coverage, awc, av);
    hgemm<<<dim3((V + 127)/128, B/128), 256, HG_SMEM>>>(p_htH, p_htL, p_vWH, p_vWL, v_b, out, V, H);
    k_rowstats<<<B, 1024>>>(out);
    k_norm<<<dim3((V/4 + 255)/256, B), 256>>>(out);
    k_attn<<<B, 512>>>(coverage, out);
    k_loss<<<1, B>>>(out);
    k_scatter<<<B, 512>>>(enc_inputs, out);
}

// round 10
// speedup vs baseline: 1.2105x; 1.2105x over previous
#include <cuda_runtime.h>
#include <cuda_bf16.h>
#include <math.h>
#include <stdint.h>

#define B 512
#define S 400
#define V 50000
#define E 512
#define H 256
#define EMB 128
#define KX (E + EMB + H)
#define G4 (4*H)
#define NPX ((V + 127) / 128)   /* 391 logits CTA columns */

#define OUT_COV    ((size_t)B*V)
#define OUT_HT     (OUT_COV  + (size_t)B*S)
#define OUT_CT     (OUT_HT   + (size_t)B*H)
#define OUT_ATTN   (OUT_CT   + (size_t)B*H)
#define OUT_LOSS   (OUT_ATTN + (size_t)B*S)

__device__ float g_ctxp[4][B*E];
__device__ float g_embed[B*EMB];
__device__ float g_bcat[G4];
__device__ float g_gates[B*G4];
__device__ float g_cwp[4*B];
__device__ float g_exw[B];
__device__ float g_pgen[B];
__device__ float g_wsapp[B*H];
__device__ float g_bias2[H];
__device__ float g_energy[B*S];
__device__ float g_covpart[B];
__device__ float g_rowinv[B];
__device__ float g_psum[(size_t)B*NPX];

__device__ __nv_bfloat16 g_WcatH[G4*KX], g_WcatL[G4*KX];
__device__ __nv_bfloat16 g_xcatH[B*KX],  g_xcatL[B*KX];
__device__ __nv_bfloat16 g_awhH[H*E],    g_awhL[H*E];
__device__ __nv_bfloat16 g_awsH[H*H],    g_awsL[H*H];
__device__ __nv_bfloat16 g_vWH[(size_t)V*H], g_vWL[(size_t)V*H];
__device__ __nv_bfloat16 g_htH[B*H],     g_htL[B*H];

// ---------- helpers ----------
__device__ __forceinline__ uint32_t smem_u32(const void* p) {
    uint32_t a;
    asm("{ .reg .u64 t; cvta.to.shared.u64 t, %1; cvt.u32.u64 %0, t; }" : "=r"(a) : "l"(p));
    return a;
}
__device__ __forceinline__ void ldm_x4(uint32_t* r, uint32_t addr) {
    asm volatile("ldmatrix.sync.aligned.m8n8.x4.shared.b16 {%0,%1,%2,%3}, [%4];"
        : "=r"(r[0]), "=r"(r[1]), "=r"(r[2]), "=r"(r[3]) : "r"(addr));
}
__device__ __forceinline__ void mma16816(float* d, const uint32_t* a, const uint32_t* b) {
    asm volatile("mma.sync.aligned.m16n8k16.row.col.f32.bf16.bf16.f32 "
        "{%0,%1,%2,%3}, {%4,%5,%6,%7}, {%8,%9}, {%0,%1,%2,%3};"
        : "+f"(d[0]), "+f"(d[1]), "+f"(d[2]), "+f"(d[3])
        : "r"(a[0]), "r"(a[1]), "r"(a[2]), "r"(a[3]), "r"(b[0]), "r"(b[1]));
}
__device__ __forceinline__ void cpa(uint32_t dst, const void* src) {
    asm volatile("cp.async.cg.shared.global [%0], [%1], 16;" :: "r"(dst), "l"(src));
}
__device__ __forceinline__ void cpa_z(uint32_t dst, const void* src, int sz) {
    asm volatile("cp.async.cg.shared.global [%0], [%1], 16, %2;" :: "r"(dst), "l"(src), "r"(sz));
}
#define CP_COMMIT() asm volatile("cp.async.commit_group;" ::: "memory")
#define CP_WAIT1()  asm volatile("cp.async.wait_group 1;" ::: "memory")
#define CP_WAIT0()  asm volatile("cp.async.wait_group 0;" ::: "memory")

__device__ __forceinline__ void st_hilo(char* hiB, char* loB, int row, int k, float4 v) {
    int off = row*80 + k*2;
    __nv_bfloat16 h0 = __float2bfloat16(v.x), h1 = __float2bfloat16(v.y),
                  h2 = __float2bfloat16(v.z), h3 = __float2bfloat16(v.w);
    __nv_bfloat16 l0 = __float2bfloat16(v.x - __bfloat162float(h0)),
                  l1 = __float2bfloat16(v.y - __bfloat162float(h1)),
                  l2 = __float2bfloat16(v.z - __bfloat162float(h2)),
                  l3 = __float2bfloat16(v.w - __bfloat162float(h3));
    *(__nv_bfloat162*)(hiB + off)     = __halves2bfloat162(h0, h1);
    *(__nv_bfloat162*)(hiB + off + 4) = __halves2bfloat162(h2, h3);
    *(__nv_bfloat162*)(loB + off)     = __halves2bfloat162(l0, l1);
    *(__nv_bfloat162*)(loB + off + 4) = __halves2bfloat162(l2, l3);
}
__device__ __forceinline__ void split2(float v, __nv_bfloat16* hp, __nv_bfloat16* lp) {
    __nv_bfloat16 h = __float2bfloat16(v);
    *hp = h;
    *lp = __float2bfloat16(v - __bfloat162float(h));
}
// one 32-k step for a 32x64 warp tile: 3-term bf16
__device__ __forceinline__ void mma_step(float acc[2][8][4],
    uint32_t aHa, uint32_t aLa, uint32_t bHa, uint32_t bLa) {
    uint32_t aH[2][4], aL[2][4], bH[4][4], bL[4][4];
    #pragma unroll
    for (int mt = 0; mt < 2; mt++) { ldm_x4(aH[mt], aHa + mt*1280); ldm_x4(aL[mt], aLa + mt*1280); }
    #pragma unroll
    for (int np = 0; np < 4; np++) { ldm_x4(bH[np], bHa + np*1280); ldm_x4(bL[np], bLa + np*1280); }
    #pragma unroll
    for (int mt = 0; mt < 2; mt++)
        #pragma unroll
        for (int np = 0; np < 4; np++) {
            mma16816(acc[mt][2*np],   aH[mt], bH[np]);
            mma16816(acc[mt][2*np+1], aH[mt], bH[np]+2);
            mma16816(acc[mt][2*np],   aH[mt], bL[np]);
            mma16816(acc[mt][2*np+1], aH[mt], bL[np]+2);
            mma16816(acc[mt][2*np],   aL[mt], bH[np]);
            mma16816(acc[mt][2*np+1], aL[mt], bH[np]+2);
        }
}

__device__ __forceinline__ float sigmoidf_(float x) { return 1.f / (1.f + expf(-x)); }

__device__ __forceinline__ float blk_sum(float v, float* red) {
    int tid = threadIdx.x;
    #pragma unroll
    for (int o = 16; o; o >>= 1) v += __shfl_down_sync(0xffffffffu, v, o);
    if ((tid & 31) == 0) red[tid >> 5] = v;
    __syncthreads();
    float r;
    if (tid < 32) {
        int nw = (blockDim.x + 31) >> 5;
        r = (tid < nw) ? red[tid] : 0.f;
        #pragma unroll
        for (int o = 16; o; o >>= 1) r += __shfl_down_sync(0xffffffffu, r, o);
        if (tid == 0) red[0] = r;
    }
    __syncthreads();
    r = red[0];
    __syncthreads();
    return r;
}
__device__ __forceinline__ float blk_max(float v, float* red) {
    int tid = threadIdx.x;
    #pragma unroll
    for (int o = 16; o; o >>= 1) v = fmaxf(v, __shfl_down_sync(0xffffffffu, v, o));
    if ((tid & 31) == 0) red[tid >> 5] = v;
    __syncthreads();
    float r;
    if (tid < 32) {
        int nw = (blockDim.x + 31) >> 5;
        r = (tid < nw) ? red[tid] : -1e30f;
        #pragma unroll
        for (int o = 16; o; o >>= 1) r = fmaxf(r, __shfl_down_sync(0xffffffffu, r, o));
        if (tid == 0) red[0] = r;
    }
    __syncthreads();
    r = red[0];
    __syncthreads();
    return r;
}

// ---------- fp32 -> bf16 hi/lo converter ----------
__global__ void k_cvt(const float* __restrict__ src, __nv_bfloat16* __restrict__ hi,
                      __nv_bfloat16* __restrict__ lo, int n) {
    int idx = (blockIdx.x*blockDim.x + threadIdx.x) * 4;
    if (idx < n) {
        float4 v = *(const float4*)(src + idx);
        __nv_bfloat16 h0, h1, h2, h3, l0, l1, l2, l3;
        split2(v.x, &h0, &l0); split2(v.y, &h1, &l1);
        split2(v.z, &h2, &l2); split2(v.w, &h3, &l3);
        *(__nv_bfloat162*)(hi + idx)     = __halves2bfloat162(h0, h1);
        *(__nv_bfloat162*)(hi + idx + 2) = __halves2bfloat162(h2, h3);
        *(__nv_bfloat162*)(lo + idx)     = __halves2bfloat162(l0, l1);
        *(__nv_bfloat162*)(lo + idx + 2) = __halves2bfloat162(l2, l3);
    }
}

// ---------- context (S quarters), embed, p_gen partials ----------
__global__ void k_context(const float* __restrict__ attn, const float* __restrict__ enc_out,
                          const int* __restrict__ dec_input, const float* __restrict__ emb_table,
                          const float* __restrict__ wh, const float* __restrict__ wx) {
    int b = blockIdx.x, q = blockIdx.y, tid = threadIdx.x;
    __shared__ float sa[S/4];
    __shared__ float red[32];
    int s0 = q * (S/4);
    for (int s = tid; s < S/4; s += 256) sa[s] = attn[(size_t)b*S + s0 + s];
    __syncthreads();
    const float* eb = enc_out + ((size_t)b*S + s0)*E;
    float a0 = 0.f, a1 = 0.f;
    #pragma unroll 4
    for (int s = 0; s < S/4; s++) {
        float a = sa[s];
        a0 += a * eb[(size_t)s*E + tid];
        a1 += a * eb[(size_t)s*E + 256 + tid];
    }
    g_ctxp[q][b*E + tid]       = a0;
    g_ctxp[q][b*E + 256 + tid] = a1;
    float cw = blk_sum(a0*wh[tid] + a1*wh[256+tid], red);
    if (tid == 0) g_cwp[q*B + b] = cw;
    if (q == 0) {
        float ew = 0.f;
        if (tid < EMB) {
            float e = emb_table[(size_t)dec_input[b]*EMB + tid];
            g_embed[b*EMB + tid] = e;
            ew = e * wx[tid];
        }
        float exw = blk_sum(ew, red);
        if (tid == 0) g_exw[b] = exw;
    }
}

__global__ void k_packw(const float* __restrict__ W_ih, const float* __restrict__ W_hh,
                        const float* __restrict__ b_ih, const float* __restrict__ b_hh,
                        const float* __restrict__ aws_b, const float* __restrict__ awh_b) {
    int idx = blockIdx.x*blockDim.x + threadIdx.x;
    if (idx < G4*KX) {
        int n = idx / KX, k = idx % KX;
        float w = (k < E+EMB) ? W_ih[(size_t)n*(E+EMB) + k] : W_hh[(size_t)n*H + (k - (E+EMB))];
        split2(w, &g_WcatH[idx], &g_WcatL[idx]);
    }
    if (idx < G4) g_bcat[idx] = b_ih[idx] + b_hh[idx];
    if (idx < H)  g_bias2[idx] = aws_b[idx] + awh_b[idx];
}
__global__ void k_packx(const float* __restrict__ h0) {
    int idx = blockIdx.x*blockDim.x + threadIdx.x;
    if (idx < B*KX) {
        int b = idx / KX, k = idx % KX;
        float v;
        if (k < E)          v = g_ctxp[0][b*E+k] + g_ctxp[1][b*E+k] + g_ctxp[2][b*E+k] + g_ctxp[3][b*E+k];
        else if (k < E+EMB) v = g_embed[b*EMB + (k - E)];
        else                v = h0[b*H + (k - E - EMB)];
        split2(v, &g_xcatH[idx], &g_xcatL[idx]);
    }
}

// ---------- HMMA GEMM, cp.async double-buffered: tile 128x128, K-chunk 32 ----------
// expmode: store exp(acc+bias) and emit deterministic per-(row,CTA) partial sums.
#define HG_STAGE 40960
#define HG_SMEM  81920
__global__ void __launch_bounds__(256) hgemm(
        const __nv_bfloat16* __restrict__ Ah, const __nv_bfloat16* __restrict__ Al,
        const __nv_bfloat16* __restrict__ Wh, const __nv_bfloat16* __restrict__ Wl,
        const float* __restrict__ bias, float* __restrict__ C, int N, int K,
        float* __restrict__ psum) {
    extern __shared__ __align__(16) char sm[];
    uint32_t sb = smem_u32(sm);

    int tid = threadIdx.x, wid = tid >> 5, lane = tid & 31;
    int m0 = blockIdx.y * 128, n0 = blockIdx.x * 128;
    int wr = (wid & 3) * 32, wc = (wid >> 2) * 64;
    int lr = lane & 7, sect = lane >> 3;
    uint32_t aoff = (uint32_t)((wr + (sect & 1)*8 + lr)*80 + (sect >> 1)*16);
    uint32_t boff = (uint32_t)((wc + (sect >> 1)*8 + lr)*80 + (sect & 1)*16);

    int r = tid >> 1, kb = (tid & 1) * 16;
    uint32_t doff = (uint32_t)(r*80 + kb*2);
    const char* aHs = (const char*)(Ah + (size_t)(m0 + r)*K + kb);
    const char* aLs = (const char*)(Al + (size_t)(m0 + r)*K + kb);
    int n = n0 + r;
    int wsz = (n < N) ? 16 : 0;
    int nc = (n < N) ? n : 0;
    const char* wHs = (const char*)(Wh + (size_t)nc*K + kb);
    const char* wLs = (const char*)(Wl + (size_t)nc*K + kb);

    float acc[2][8][4];
    #pragma unroll
    for (int i = 0; i < 2; i++)
        #pragma unroll
        for (int j = 0; j < 8; j++)
            #pragma unroll
            for (int e = 0; e < 4; e++) acc[i][j][e] = 0.f;

    const int NC = K / 32;
    #pragma unroll
    for (int i = 0; i < 2; i++) {
        cpa(sb + doff + i*16,          aHs + i*16);
        cpa(sb + 10240 + doff + i*16,  aLs + i*16);
        cpa_z(sb + 20480 + doff + i*16, wHs + i*16, wsz);
        cpa_z(sb + 30720 + doff + i*16, wLs + i*16, wsz);
    }
    CP_COMMIT();

    for (int c = 0; c < NC; c++) {
        uint32_t st = sb + (uint32_t)((c & 1) * HG_STAGE);
        if (c + 1 < NC) {
            uint32_t st2 = sb + (uint32_t)(((c+1) & 1) * HG_STAGE);
            int ko = (c + 1) * 64;
            #pragma unroll
            for (int i = 0; i < 2; i++) {
                cpa(st2 + doff + i*16,          aHs + ko + i*16);
                cpa(st2 + 10240 + doff + i*16,  aLs + ko + i*16);
                cpa_z(st2 + 20480 + doff + i*16, wHs + ko + i*16, wsz);
                cpa_z(st2 + 30720 + doff + i*16, wLs + ko + i*16, wsz);
            }
            CP_COMMIT();
            CP_WAIT1();
        } else CP_WAIT0();
        __syncthreads();
        #pragma unroll
        for (int ks = 0; ks < 64; ks += 32)
            mma_step(acc, st + aoff + ks, st + 10240 + aoff + ks,
                          st + 20480 + boff + ks, st + 30720 + boff + ks);
        __syncthreads();
    }

    int gid = lane >> 2, t4 = lane & 3;
    if (psum == nullptr) {
        #pragma unroll
        for (int mt = 0; mt < 2; mt++)
            #pragma unroll
            for (int eh = 0; eh < 2; eh++) {
                size_t row = (size_t)(m0 + wr + mt*16 + eh*8 + gid);
                #pragma unroll
                for (int nt = 0; nt < 8; nt++) {
                    int col = n0 + wc + nt*8 + 2*t4;
                    if (col + 1 < N) {
                        float2 v;
                        v.x = acc[mt][nt][eh*2+0] + bias[col];
                        v.y = acc[mt][nt][eh*2+1] + bias[col+1];
                        *(float2*)&C[row*(size_t)N + col] = v;
                    } else if (col < N) {
                        C[row*(size_t)N + col] = acc[mt][nt][eh*2] + bias[col];
                    }
                }
            }
    } else {
        // exp epilogue + deterministic per-(row, colgroup) partials
        float* sp = (float*)sm;   // [128][2]
        int cg = wid >> 2;
        #pragma unroll
        for (int mt = 0; mt < 2; mt++)
            #pragma unroll
            for (int eh = 0; eh < 2; eh++) {
                int rloc = wr + mt*16 + eh*8 + gid;
                size_t row = (size_t)(m0 + rloc);
                float p = 0.f;
                #pragma unroll
                for (int nt = 0; nt < 8; nt++) {
                    int col = n0 + wc + nt*8 + 2*t4;
                    if (col + 1 < N) {
                        float2 v;
                        v.x = expf(acc[mt][nt][eh*2+0] + bias[col]);
                        v.y = expf(acc[mt][nt][eh*2+1] + bias[col+1]);
                        *(float2*)&C[row*(size_t)N + col] = v;
                        p += v.x + v.y;
                    } else if (col < N) {
                        float v = expf(acc[mt][nt][eh*2] + bias[col]);
                        C[row*(size_t)N + col] = v;
                        p += v;
                    }
                }
                p += __shfl_xor_sync(0xffffffffu, p, 1);
                p += __shfl_xor_sync(0xffffffffu, p, 2);
                if (t4 == 0) sp[rloc*2 + cg] = p;
            }
        __syncthreads();
        if (tid < 128)
            psum[(size_t)(m0 + tid)*NPX + blockIdx.x] = sp[tid*2] + sp[tid*2+1];
    }
}

// ---------- fused wh_app GEMM + energy: tile 64x256, 2-stage (R8 config) ----------
#define FK_STAGE 51200
#define FK_FLT   102400
#define FK_SMEM  107776
__global__ void __launch_bounds__(256) fk_whenergy(const float* __restrict__ A,
        const __nv_bfloat16* __restrict__ Wh, const __nv_bfloat16* __restrict__ Wl,
        const float* __restrict__ coverage,
        const float* __restrict__ awc, const float* __restrict__ av) {
    extern __shared__ __align__(16) char sm[];
    uint32_t sb = smem_u32(sm);
    float* swsA = (float*)(sm + FK_FLT);
    float* swsB = (float*)(sm + FK_FLT + 1024);
    float* sawc = (float*)(sm + FK_FLT + 2048);
    float* sav  = (float*)(sm + FK_FLT + 3072);
    float* scov = (float*)(sm + FK_FLT + 4096);
    float* sred = (float*)(sm + FK_FLT + 4352);

    int tid = threadIdx.x, wid = tid >> 5, lane = tid & 31;
    int m0 = blockIdx.x * 64;
    int b0 = m0 / S;
    int b1 = (b0 + 1 < B) ? b0 + 1 : b0;
    int bswitch = (b0 + 1) * S - m0;
    int wr = (wid & 1) * 32, wc = (wid >> 1) * 64;
    int lr = lane & 7, sect = lane >> 3;
    uint32_t aoff = (uint32_t)((wr + (sect & 1)*8 + lr)*80 + (sect >> 1)*16);
    uint32_t boff = (uint32_t)((wc + (sect >> 1)*8 + lr)*80 + (sect & 1)*16);

    swsA[tid] = g_wsapp[b0*H + tid];
    swsB[tid] = g_wsapp[b1*H + tid];
    sawc[tid] = awc[tid];
    sav[tid]  = av[tid];
    if (tid < 64) scov[tid] = coverage[(size_t)m0 + tid];

    const char* wHs = (const char*)(Wh + (size_t)tid*E);
    const char* wLs = (const char*)(Wl + (size_t)tid*E);
    uint32_t wdoff = (uint32_t)(tid*80);
    int ar = tid >> 2, akb = (tid & 3) * 8;
    const float* aSrc = A + (size_t)(m0 + ar)*E + akb;

    float acc[2][8][4];
    #pragma unroll
    for (int i = 0; i < 2; i++)
        #pragma unroll
        for (int j = 0; j < 8; j++)
            #pragma unroll
            for (int e = 0; e < 4; e++) acc[i][j][e] = 0.f;

    #pragma unroll
    for (int i = 0; i < 4; i++) {
        cpa(sb + wdoff + i*16,         wHs + i*16);
        cpa(sb + 20480 + wdoff + i*16, wLs + i*16);
    }
    CP_COMMIT();
    float4 aN0 = *(const float4*)(aSrc);
    float4 aN1 = *(const float4*)(aSrc + 4);

    for (int c = 0; c < E/32; c++) {
        uint32_t st = sb + (uint32_t)((c & 1) * FK_STAGE);
        char* stc = sm + (c & 1) * FK_STAGE;
        st_hilo(stc + 40960, stc + 46080, ar, akb,     aN0);
        st_hilo(stc + 40960, stc + 46080, ar, akb + 4, aN1);
        if (c + 1 < E/32) {
            uint32_t st2 = sb + (uint32_t)(((c+1) & 1) * FK_STAGE);
            int ko = (c + 1) * 64;
            #pragma unroll
            for (int i = 0; i < 4; i++) {
                cpa(st2 + wdoff + i*16,         wHs + ko + i*16);
                cpa(st2 + 20480 + wdoff + i*16, wLs + ko + i*16);
            }
            CP_COMMIT();
            aN0 = *(const float4*)(aSrc + (c+1)*32);
            aN1 = *(const float4*)(aSrc + (c+1)*32 + 4);
            CP_WAIT1();
        } else CP_WAIT0();
        __syncthreads();
        #pragma unroll
        for (int ks = 0; ks < 64; ks += 32)
            mma_step(acc, st + 40960 + aoff + ks, st + 46080 + aoff + ks,
                          st + boff + ks,         st + 20480 + boff + ks);
        __syncthreads();
    }

    int gid = lane >> 2, t4 = lane & 3;
    #pragma unroll
    for (int mt = 0; mt < 2; mt++)
        #pragma unroll
        for (int eh = 0; eh < 2; eh++) {
            int row = wr + mt*16 + eh*8 + gid;
            float c = scov[row];
            const float* sws = (row < bswitch) ? swsA : swsB;
            float p = 0.f;
            #pragma unroll
            for (int nt = 0; nt < 8; nt++)
                #pragma unroll
                for (int e2 = 0; e2 < 2; e2++) {
                    int h = wc + nt*8 + 2*t4 + e2;
                    float x = acc[mt][nt][eh*2 + e2] + sws[h] + c * sawc[h];
                    p += tanhf(x) * sav[h];
                }
            p += __shfl_xor_sync(0xffffffffu, p, 1);
            p += __shfl_xor_sync(0xffffffffu, p, 2);
            if (t4 == 0) sred[row*4 + (wid >> 1)] = p;
        }
    __syncthreads();
    if (tid < 64)
        g_energy[(size_t)m0 + tid] = sred[tid*4] + sred[tid*4+1] + sred[tid*4+2] + sred[tid*4+3];
}

// ---------- LSTM + p_gen ----------
__global__ void k_lstm(const float* __restrict__ c0, const float* __restrict__ ws,
                       float* __restrict__ out) {
    int b = blockIdx.x, h = threadIdx.x;
    __shared__ float red[32];
    const float* g = g_gates + (size_t)b*G4;
    float ig = sigmoidf_(g[h]);
    float fg = sigmoidf_(g[H + h]);
    float gg = tanhf(g[2*H + h]);
    float og = sigmoidf_(g[3*H + h]);
    float c  = fg * c0[b*H + h] + ig * gg;
    float ht = og * tanhf(c);
    out[OUT_CT + (size_t)b*H + h] = c;
    out[OUT_HT + (size_t)b*H + h] = ht;
    split2(ht, &g_htH[b*H + h], &g_htL[b*H + h]);
    float hw = blk_sum(ht * ws[h], red);
    if (h == 0)
        g_pgen[b] = sigmoidf_(g_cwp[b] + g_cwp[B+b] + g_cwp[2*B+b] + g_cwp[3*B+b] + hw + g_exw[b]);
}

// ---------- vocab softmax: reduce per-CTA partials, then scale ----------
__global__ void k_rowsum() {
    int b = blockIdx.x, tid = threadIdx.x;   // 512 threads
    __shared__ float red[32];
    float s = 0.f;
    for (int i = tid; i < NPX; i += 512) s += g_psum[(size_t)b*NPX + i];
    float t = blk_sum(s, red);
    if (tid == 0) g_rowinv[b] = 1.f / t;
}
__global__ void k_norm(float* __restrict__ out) {
    int b = blockIdx.y;
    int i = (blockIdx.x*blockDim.x + threadIdx.x) * 4;
    if (i < V) {
        float4* p = (float4*)(out + (size_t)b*V + i);
        float4 v = *p;
        float sc = g_pgen[b] * g_rowinv[b];
        v.x *= sc; v.y *= sc; v.z *= sc; v.w *= sc;
        *p = v;
    }
}

// ---------- attention softmax + coverage + loss ----------
__global__ void k_attn(const float* __restrict__ coverage, float* __restrict__ out) {
    int b = blockIdx.x, tid = threadIdx.x;
    __shared__ float red[32];
    float e = (tid < S) ? g_energy[b*S + tid] : -1e30f;
    float m = blk_max(e, red);
    float ex = (tid < S) ? expf(e - m) : 0.f;
    float sum = blk_sum(ex, red);
    float part = 0.f;
    if (tid < S) {
        float a = ex / sum;
        out[OUT_ATTN + (size_t)b*S + tid] = a;
        float c = coverage[(size_t)b*S + tid];
        out[OUT_COV + (size_t)b*S + tid] = c + a;
        part = fminf(a, c);
    }
    float ps = blk_sum(part, red);
    if (tid == 0) g_covpart[b] = ps;
}
__global__ void k_loss(float* __restrict__ out) {
    __shared__ float red[32];
    float s = blk_sum(g_covpart[threadIdx.x], red);
    if (threadIdx.x == 0) out[OUT_LOSS] = s;
}

// ---------- scatter (last-s-wins) ----------
__global__ void k_scatter(const int* __restrict__ enc_inputs, float* __restrict__ out) {
    int b = blockIdx.x, tid = threadIdx.x;
    __shared__ int   sidx[S];
    __shared__ float sat[S];
    if (tid < S) {
        sidx[tid] = enc_inputs[(size_t)b*S + tid];
        sat[tid]  = out[OUT_ATTN + (size_t)b*S + tid];
    }
    __syncthreads();
    if (tid < S) {
        int v = sidx[tid];
        bool win = true;
        for (int s2 = tid + 1; s2 < S; s2++)
            if (sidx[s2] == v) { win = false; break; }
        if (win) out[(size_t)b*V + v] += (1.f - g_pgen[b]) * sat[tid];
    }
}

// ---------- host ----------
extern "C" void kernel_launch(void* const* d_in, const int* in_sizes, int n_in,
                              void* d_out, int out_size) {
    const float* coverage   = (const float*)d_in[0];
    const float* enc_out    = (const float*)d_in[1];
    const float* h0         = (const float*)d_in[2];
    const float* c0         = (const float*)d_in[3];
    const float* attn       = (const float*)d_in[4];
    const int*   dec_input  = (const int*)d_in[5];
    const int*   enc_inputs = (const int*)d_in[6];
    const float* emb_table  = (const float*)d_in[7];
    const float* W_ih       = (const float*)d_in[8];
    const float* W_hh       = (const float*)d_in[9];
    const float* b_ih       = (const float*)d_in[10];
    const float* b_hh       = (const float*)d_in[11];
    const float* awh_W      = (const float*)d_in[12];
    const float* awh_b      = (const float*)d_in[13];
    const float* aws_W      = (const float*)d_in[14];
    const float* aws_b      = (const float*)d_in[15];
    const float* awc        = (const float*)d_in[16];
    const float* av         = (const float*)d_in[17];
    const float* wh         = (const float*)d_in[18];
    const float* ws         = (const float*)d_in[19];
    const float* wx         = (const float*)d_in[20];
    const float* v_W        = (const float*)d_in[21];
    const float* v_b        = (const float*)d_in[22];
    float* out = (float*)d_out;

    float *p_bcat, *p_gates, *p_wsapp, *p_bias2, *p_psum;
    __nv_bfloat16 *p_WcatH, *p_WcatL, *p_xcatH, *p_xcatL, *p_awhH, *p_awhL;
    __nv_bfloat16 *p_awsH, *p_awsL, *p_vWH, *p_vWL, *p_htH, *p_htL;
    cudaGetSymbolAddress((void**)&p_bcat,  g_bcat);
    cudaGetSymbolAddress((void**)&p_gates, g_gates);
    cudaGetSymbolAddress((void**)&p_wsapp, g_wsapp);
    cudaGetSymbolAddress((void**)&p_bias2, g_bias2);
    cudaGetSymbolAddress((void**)&p_psum,  g_psum);
    cudaGetSymbolAddress((void**)&p_WcatH, g_WcatH);
    cudaGetSymbolAddress((void**)&p_WcatL, g_WcatL);
    cudaGetSymbolAddress((void**)&p_xcatH, g_xcatH);
    cudaGetSymbolAddress((void**)&p_xcatL, g_xcatL);
    cudaGetSymbolAddress((void**)&p_awhH,  g_awhH);
    cudaGetSymbolAddress((void**)&p_awhL,  g_awhL);
    cudaGetSymbolAddress((void**)&p_awsH,  g_awsH);
    cudaGetSymbolAddress((void**)&p_awsL,  g_awsL);
    cudaGetSymbolAddress((void**)&p_vWH,   g_vWH);
    cudaGetSymbolAddress((void**)&p_vWL,   g_vWL);
    cudaGetSymbolAddress((void**)&p_htH,   g_htH);
    cudaGetSymbolAddress((void**)&p_htL,   g_htL);

    cudaFuncSetAttribute(fk_whenergy, cudaFuncAttributeMaxDynamicSharedMemorySize, FK_SMEM);
    cudaFuncSetAttribute(hgemm,       cudaFuncAttributeMaxDynamicSharedMemorySize, HG_SMEM);

    k_context<<<dim3(B, 4), 256>>>(attn, enc_out, dec_input, emb_table, wh, wx);
    k_packw<<<(G4*KX + 255)/256, 256>>>(W_ih, W_hh, b_ih, b_hh, aws_b, awh_b);
    k_cvt<<<(H*E/4 + 255)/256, 256>>>(awh_W, p_awhH, p_awhL, H*E);
    k_cvt<<<(H*H/4 + 255)/256, 256>>>(aws_W, p_awsH, p_awsL, H*H);
    k_cvt<<<(V*H/4 + 255)/256, 256>>>(v_W, p_vWH, p_vWL, V*H);
    k_packx<<<(B*KX + 255)/256, 256>>>(h0);
    hgemm<<<dim3(G4/128, B/128), 256, HG_SMEM>>>(p_xcatH, p_xcatL, p_WcatH, p_WcatL, p_bcat, p_gates, G4, KX, nullptr);
    k_lstm<<<B, 256>>>(c0, ws, out);
    hgemm<<<dim3(H/128, B/128), 256, HG_SMEM>>>(p_htH, p_htL, p_awsH, p_awsL, p_bias2, p_wsapp, H, H, nullptr);
    fk_whenergy<<<(B*S)/64, 256, FK_SMEM>>>(enc_out, p_awhH, p_awhL, coverage, awc, av);
    // logits -> exp(logits) + per-CTA row partial sums
    hgemm<<<dim3(NPX, B/128), 256, HG_SMEM>>>(p_htH, p_htL, p_vWH, p_vWL, v_b, out, V, H, p_psum);
    k_rowsum<<<B, 512>>>();
    k_norm<<<dim3((V/4 + 255)/256, B), 256>>>(out);
    k_attn<<<B, 512>>>(coverage, out);
    k_loss<<<1, B>>>(out);
    k_scatter<<<B, 512>>>(enc_inputs, out);
}

// round 11
// speedup vs baseline: 1.2202x; 1.0081x over previous
#include <cuda_runtime.h>
#include <cuda_bf16.h>
#include <math.h>
#include <stdint.h>

#define B 512
#define S 400
#define V 50000
#define E 512
#define H 256
#define EMB 128
#define KX (E + EMB + H)
#define G4 (4*H)
#define NPX ((V + 127) / 128)

#define OUT_COV    ((size_t)B*V)
#define OUT_HT     (OUT_COV  + (size_t)B*S)
#define OUT_CT     (OUT_HT   + (size_t)B*H)
#define OUT_ATTN   (OUT_CT   + (size_t)B*H)
#define OUT_LOSS   (OUT_ATTN + (size_t)B*S)

__device__ float g_ctxp[4][B*E];
__device__ float g_embed[B*EMB];
__device__ float g_bcat[G4];
__device__ float g_gates[B*G4];
__device__ float g_cwp[4*B];
__device__ float g_exw[B];
__device__ float g_pgen[B];
__device__ float g_wsapp[B*H];
__device__ float g_bias2[H];
__device__ float g_energy[B*S];
__device__ float g_covpart[B];
__device__ float g_rowinv[B];
__device__ float g_psum[(size_t)B*NPX];

__device__ __nv_bfloat16 g_WcatH[G4*KX], g_WcatL[G4*KX];
__device__ __nv_bfloat16 g_xcatH[B*KX],  g_xcatL[B*KX];
__device__ __nv_bfloat16 g_awhH[H*E],    g_awhL[H*E];
__device__ __nv_bfloat16 g_awsH[H*H],    g_awsL[H*H];
__device__ __nv_bfloat16 g_vWH[(size_t)V*H], g_vWL[(size_t)V*H];
__device__ __nv_bfloat16 g_htH[B*H],     g_htL[B*H];

// ---------- helpers ----------
__device__ __forceinline__ uint32_t smem_u32(const void* p) {
    uint32_t a;
    asm("{ .reg .u64 t; cvta.to.shared.u64 t, %1; cvt.u32.u64 %0, t; }" : "=r"(a) : "l"(p));
    return a;
}
__device__ __forceinline__ void ldm_x4(uint32_t* r, uint32_t addr) {
    asm volatile("ldmatrix.sync.aligned.m8n8.x4.shared.b16 {%0,%1,%2,%3}, [%4];"
        : "=r"(r[0]), "=r"(r[1]), "=r"(r[2]), "=r"(r[3]) : "r"(addr));
}
__device__ __forceinline__ void mma16816(float* d, const uint32_t* a, const uint32_t* b) {
    asm volatile("mma.sync.aligned.m16n8k16.row.col.f32.bf16.bf16.f32 "
        "{%0,%1,%2,%3}, {%4,%5,%6,%7}, {%8,%9}, {%0,%1,%2,%3};"
        : "+f"(d[0]), "+f"(d[1]), "+f"(d[2]), "+f"(d[3])
        : "r"(a[0]), "r"(a[1]), "r"(a[2]), "r"(a[3]), "r"(b[0]), "r"(b[1]));
}
__device__ __forceinline__ void cpa(uint32_t dst, const void* src) {
    asm volatile("cp.async.cg.shared.global [%0], [%1], 16;" :: "r"(dst), "l"(src));
}
__device__ __forceinline__ void cpa_z(uint32_t dst, const void* src, int sz) {
    asm volatile("cp.async.cg.shared.global [%0], [%1], 16, %2;" :: "r"(dst), "l"(src), "r"(sz));
}
#define CP_COMMIT() asm volatile("cp.async.commit_group;" ::: "memory")
#define CP_WAIT1()  asm volatile("cp.async.wait_group 1;" ::: "memory")
#define CP_WAIT0()  asm volatile("cp.async.wait_group 0;" ::: "memory")

__device__ __forceinline__ void st_hilo(char* hiB, char* loB, int row, int k, float4 v) {
    int off = row*80 + k*2;
    __nv_bfloat16 h0 = __float2bfloat16(v.x), h1 = __float2bfloat16(v.y),
                  h2 = __float2bfloat16(v.z), h3 = __float2bfloat16(v.w);
    __nv_bfloat16 l0 = __float2bfloat16(v.x - __bfloat162float(h0)),
                  l1 = __float2bfloat16(v.y - __bfloat162float(h1)),
                  l2 = __float2bfloat16(v.z - __bfloat162float(h2)),
                  l3 = __float2bfloat16(v.w - __bfloat162float(h3));
    *(__nv_bfloat162*)(hiB + off)     = __halves2bfloat162(h0, h1);
    *(__nv_bfloat162*)(hiB + off + 4) = __halves2bfloat162(h2, h3);
    *(__nv_bfloat162*)(loB + off)     = __halves2bfloat162(l0, l1);
    *(__nv_bfloat162*)(loB + off + 4) = __halves2bfloat162(l2, l3);
}
__device__ __forceinline__ void split2(float v, __nv_bfloat16* hp, __nv_bfloat16* lp) {
    __nv_bfloat16 h = __float2bfloat16(v);
    *hp = h;
    *lp = __float2bfloat16(v - __bfloat162float(h));
}
__device__ __forceinline__ void mma_step(float acc[2][8][4],
    uint32_t aHa, uint32_t aLa, uint32_t bHa, uint32_t bLa) {
    uint32_t aH[2][4], aL[2][4], bH[4][4], bL[4][4];
    #pragma unroll
    for (int mt = 0; mt < 2; mt++) { ldm_x4(aH[mt], aHa + mt*1280); ldm_x4(aL[mt], aLa + mt*1280); }
    #pragma unroll
    for (int np = 0; np < 4; np++) { ldm_x4(bH[np], bHa + np*1280); ldm_x4(bL[np], bLa + np*1280); }
    #pragma unroll
    for (int mt = 0; mt < 2; mt++)
        #pragma unroll
        for (int np = 0; np < 4; np++) {
            mma16816(acc[mt][2*np],   aH[mt], bH[np]);
            mma16816(acc[mt][2*np+1], aH[mt], bH[np]+2);
            mma16816(acc[mt][2*np],   aH[mt], bL[np]);
            mma16816(acc[mt][2*np+1], aH[mt], bL[np]+2);
            mma16816(acc[mt][2*np],   aL[mt], bH[np]);
            mma16816(acc[mt][2*np+1], aL[mt], bH[np]+2);
        }
}

__device__ __forceinline__ float sigmoidf_(float x) { return 1.f / (1.f + expf(-x)); }

__device__ __forceinline__ float blk_sum(float v, float* red) {
    int tid = threadIdx.x;
    #pragma unroll
    for (int o = 16; o; o >>= 1) v += __shfl_down_sync(0xffffffffu, v, o);
    if ((tid & 31) == 0) red[tid >> 5] = v;
    __syncthreads();
    float r;
    if (tid < 32) {
        int nw = (blockDim.x + 31) >> 5;
        r = (tid < nw) ? red[tid] : 0.f;
        #pragma unroll
        for (int o = 16; o; o >>= 1) r += __shfl_down_sync(0xffffffffu, r, o);
        if (tid == 0) red[0] = r;
    }
    __syncthreads();
    r = red[0];
    __syncthreads();
    return r;
}
__device__ __forceinline__ float blk_max(float v, float* red) {
    int tid = threadIdx.x;
    #pragma unroll
    for (int o = 16; o; o >>= 1) v = fmaxf(v, __shfl_down_sync(0xffffffffu, v, o));
    if ((tid & 31) == 0) red[tid >> 5] = v;
    __syncthreads();
    float r;
    if (tid < 32) {
        int nw = (blockDim.x + 31) >> 5;
        r = (tid < nw) ? red[tid] : -1e30f;
        #pragma unroll
        for (int o = 16; o; o >>= 1) r = fmaxf(r, __shfl_down_sync(0xffffffffu, r, o));
        if (tid == 0) red[0] = r;
    }
    __syncthreads();
    r = red[0];
    __syncthreads();
    return r;
}

// ---------- fp32 -> bf16 hi/lo converters ----------
__global__ void k_cvt(const float* __restrict__ src, __nv_bfloat16* __restrict__ hi,
                      __nv_bfloat16* __restrict__ lo, int n) {
    int idx = (blockIdx.x*blockDim.x + threadIdx.x) * 4;
    if (idx < n) {
        float4 v = *(const float4*)(src + idx);
        __nv_bfloat16 h0, h1, h2, h3, l0, l1, l2, l3;
        split2(v.x, &h0, &l0); split2(v.y, &h1, &l1);
        split2(v.z, &h2, &l2); split2(v.w, &h3, &l3);
        *(__nv_bfloat162*)(hi + idx)     = __halves2bfloat162(h0, h1);
        *(__nv_bfloat162*)(hi + idx + 2) = __halves2bfloat162(h2, h3);
        *(__nv_bfloat162*)(lo + idx)     = __halves2bfloat162(l0, l1);
        *(__nv_bfloat162*)(lo + idx + 2) = __halves2bfloat162(l2, l3);
    }
}
// two-tensor variant (awh then aws), one launch
__global__ void k_cvt2(const float* __restrict__ sa, __nv_bfloat16* __restrict__ ah,
                       __nv_bfloat16* __restrict__ al, int na,
                       const float* __restrict__ sb2, __nv_bfloat16* __restrict__ bh,
                       __nv_bfloat16* __restrict__ bl, int nb) {
    int idx = (blockIdx.x*blockDim.x + threadIdx.x) * 4;
    const float* src; __nv_bfloat16 *hi, *lo;
    if (idx < na) { src = sa + idx; hi = ah + idx; lo = al + idx; }
    else {
        int j = idx - na;
        if (j >= nb) return;
        src = sb2 + j; hi = bh + j; lo = bl + j;
    }
    float4 v = *(const float4*)src;
    __nv_bfloat16 h0, h1, h2, h3, l0, l1, l2, l3;
    split2(v.x, &h0, &l0); split2(v.y, &h1, &l1);
    split2(v.z, &h2, &l2); split2(v.w, &h3, &l3);
    *(__nv_bfloat162*)(hi)     = __halves2bfloat162(h0, h1);
    *(__nv_bfloat162*)(hi + 2) = __halves2bfloat162(h2, h3);
    *(__nv_bfloat162*)(lo)     = __halves2bfloat162(l0, l1);
    *(__nv_bfloat162*)(lo + 2) = __halves2bfloat162(l2, l3);
}

// ---------- context: float4 loads, S-range split across thread halves ----------
__global__ void k_context(const float* __restrict__ attn, const float* __restrict__ enc_out,
                          const int* __restrict__ dec_input, const float* __restrict__ emb_table,
                          const float* __restrict__ wh, const float* __restrict__ wx) {
    int b = blockIdx.x, q = blockIdx.y, tid = threadIdx.x;
    int half = tid >> 7, lt = tid & 127;
    __shared__ float sa[2][S/8];
    __shared__ float sctx[E];
    __shared__ float red[32];
    int s0 = q * (S/4) + half * (S/8);
    for (int i = lt; i < S/8; i += 128) sa[half][i] = attn[(size_t)b*S + s0 + i];
    __syncthreads();
    const float* eb = enc_out + ((size_t)b*S + s0)*E;
    float4 acc = make_float4(0.f, 0.f, 0.f, 0.f);
    #pragma unroll 5
    for (int s = 0; s < S/8; s++) {
        float a = sa[half][s];
        float4 v = *(const float4*)(eb + (size_t)s*E + lt*4);
        acc.x += a*v.x; acc.y += a*v.y; acc.z += a*v.z; acc.w += a*v.w;
    }
    if (half == 0) *(float4*)(sctx + lt*4) = acc;
    __syncthreads();
    float cwp = 0.f;
    if (half == 1) {
        float4 o = *(const float4*)(sctx + lt*4);
        acc.x += o.x; acc.y += o.y; acc.z += o.z; acc.w += o.w;
        *(float4*)(&g_ctxp[q][b*E + lt*4]) = acc;
        cwp = acc.x*wh[lt*4] + acc.y*wh[lt*4+1] + acc.z*wh[lt*4+2] + acc.w*wh[lt*4+3];
    }
    float cw = blk_sum(cwp, red);
    if (tid == 0) g_cwp[q*B + b] = cw;
    if (q == 0) {
        float ew = 0.f;
        if (tid < EMB) {
            float e = emb_table[(size_t)dec_input[b]*EMB + tid];
            g_embed[b*EMB + tid] = e;
            ew = e * wx[tid];
        }
        float exw = blk_sum(ew, red);
        if (tid == 0) g_exw[b] = exw;
    }
}

__global__ void k_packw(const float* __restrict__ W_ih, const float* __restrict__ W_hh,
                        const float* __restrict__ b_ih, const float* __restrict__ b_hh,
                        const float* __restrict__ aws_b, const float* __restrict__ awh_b) {
    int idx = blockIdx.x*blockDim.x + threadIdx.x;
    if (idx < G4*KX) {
        int n = idx / KX, k = idx % KX;
        float w = (k < E+EMB) ? W_ih[(size_t)n*(E+EMB) + k] : W_hh[(size_t)n*H + (k - (E+EMB))];
        split2(w, &g_WcatH[idx], &g_WcatL[idx]);
    }
    if (idx < G4) g_bcat[idx] = b_ih[idx] + b_hh[idx];
    if (idx < H)  g_bias2[idx] = aws_b[idx] + awh_b[idx];
}
__global__ void k_packx(const float* __restrict__ h0) {
    int idx = blockIdx.x*blockDim.x + threadIdx.x;
    if (idx < B*KX) {
        int b = idx / KX, k = idx % KX;
        float v;
        if (k < E)          v = g_ctxp[0][b*E+k] + g_ctxp[1][b*E+k] + g_ctxp[2][b*E+k] + g_ctxp[3][b*E+k];
        else if (k < E+EMB) v = g_embed[b*EMB + (k - E)];
        else                v = h0[b*H + (k - E - EMB)];
        split2(v, &g_xcatH[idx], &g_xcatL[idx]);
    }
}

// ---------- HMMA GEMM, cp.async double-buffered: tile 128x128, K-chunk 32 ----------
#define HG_STAGE 40960
#define HG_SMEM  81920
__global__ void __launch_bounds__(256) hgemm(
        const __nv_bfloat16* __restrict__ Ah, const __nv_bfloat16* __restrict__ Al,
        const __nv_bfloat16* __restrict__ Wh, const __nv_bfloat16* __restrict__ Wl,
        const float* __restrict__ bias, float* __restrict__ C, int N, int K,
        float* __restrict__ psum) {
    extern __shared__ __align__(16) char sm[];
    uint32_t sb = smem_u32(sm);

    int tid = threadIdx.x, wid = tid >> 5, lane = tid & 31;
    int m0 = blockIdx.y * 128, n0 = blockIdx.x * 128;
    int wr = (wid & 3) * 32, wc = (wid >> 2) * 64;
    int lr = lane & 7, sect = lane >> 3;
    uint32_t aoff = (uint32_t)((wr + (sect & 1)*8 + lr)*80 + (sect >> 1)*16);
    uint32_t boff = (uint32_t)((wc + (sect >> 1)*8 + lr)*80 + (sect & 1)*16);

    int r = tid >> 1, kb = (tid & 1) * 16;
    uint32_t doff = (uint32_t)(r*80 + kb*2);
    const char* aHs = (const char*)(Ah + (size_t)(m0 + r)*K + kb);
    const char* aLs = (const char*)(Al + (size_t)(m0 + r)*K + kb);
    int n = n0 + r;
    int wsz = (n < N) ? 16 : 0;
    int nc = (n < N) ? n : 0;
    const char* wHs = (const char*)(Wh + (size_t)nc*K + kb);
    const char* wLs = (const char*)(Wl + (size_t)nc*K + kb);

    float acc[2][8][4];
    #pragma unroll
    for (int i = 0; i < 2; i++)
        #pragma unroll
        for (int j = 0; j < 8; j++)
            #pragma unroll
            for (int e = 0; e < 4; e++) acc[i][j][e] = 0.f;

    const int NC = K / 32;
    #pragma unroll
    for (int i = 0; i < 2; i++) {
        cpa(sb + doff + i*16,          aHs + i*16);
        cpa(sb + 10240 + doff + i*16,  aLs + i*16);
        cpa_z(sb + 20480 + doff + i*16, wHs + i*16, wsz);
        cpa_z(sb + 30720 + doff + i*16, wLs + i*16, wsz);
    }
    CP_COMMIT();

    for (int c = 0; c < NC; c++) {
        uint32_t st = sb + (uint32_t)((c & 1) * HG_STAGE);
        if (c + 1 < NC) {
            uint32_t st2 = sb + (uint32_t)(((c+1) & 1) * HG_STAGE);
            int ko = (c + 1) * 64;
            #pragma unroll
            for (int i = 0; i < 2; i++) {
                cpa(st2 + doff + i*16,          aHs + ko + i*16);
                cpa(st2 + 10240 + doff + i*16,  aLs + ko + i*16);
                cpa_z(st2 + 20480 + doff + i*16, wHs + ko + i*16, wsz);
                cpa_z(st2 + 30720 + doff + i*16, wLs + ko + i*16, wsz);
            }
            CP_COMMIT();
            CP_WAIT1();
        } else CP_WAIT0();
        __syncthreads();
        #pragma unroll
        for (int ks = 0; ks < 64; ks += 32)
            mma_step(acc, st + aoff + ks, st + 10240 + aoff + ks,
                          st + 20480 + boff + ks, st + 30720 + boff + ks);
        __syncthreads();
    }

    int gid = lane >> 2, t4 = lane & 3;
    if (psum == nullptr) {
        #pragma unroll
        for (int mt = 0; mt < 2; mt++)
            #pragma unroll
            for (int eh = 0; eh < 2; eh++) {
                size_t row = (size_t)(m0 + wr + mt*16 + eh*8 + gid);
                #pragma unroll
                for (int nt = 0; nt < 8; nt++) {
                    int col = n0 + wc + nt*8 + 2*t4;
                    if (col + 1 < N) {
                        float2 v;
                        v.x = acc[mt][nt][eh*2+0] + bias[col];
                        v.y = acc[mt][nt][eh*2+1] + bias[col+1];
                        *(float2*)&C[row*(size_t)N + col] = v;
                    } else if (col < N) {
                        C[row*(size_t)N + col] = acc[mt][nt][eh*2] + bias[col];
                    }
                }
            }
    } else {
        float* sp = (float*)sm;
        int cg = wid >> 2;
        #pragma unroll
        for (int mt = 0; mt < 2; mt++)
            #pragma unroll
            for (int eh = 0; eh < 2; eh++) {
                int rloc = wr + mt*16 + eh*8 + gid;
                size_t row = (size_t)(m0 + rloc);
                float p = 0.f;
                #pragma unroll
                for (int nt = 0; nt < 8; nt++) {
                    int col = n0 + wc + nt*8 + 2*t4;
                    if (col + 1 < N) {
                        float2 v;
                        v.x = expf(acc[mt][nt][eh*2+0] + bias[col]);
                        v.y = expf(acc[mt][nt][eh*2+1] + bias[col+1]);
                        *(float2*)&C[row*(size_t)N + col] = v;
                        p += v.x + v.y;
                    } else if (col < N) {
                        float v = expf(acc[mt][nt][eh*2] + bias[col]);
                        C[row*(size_t)N + col] = v;
                        p += v;
                    }
                }
                p += __shfl_xor_sync(0xffffffffu, p, 1);
                p += __shfl_xor_sync(0xffffffffu, p, 2);
                if (t4 == 0) sp[rloc*2 + cg] = p;
            }
        __syncthreads();
        if (tid < 128)
            psum[(size_t)(m0 + tid)*NPX + blockIdx.x] = sp[tid*2] + sp[tid*2+1];
    }
}

// ---------- fused wh_app GEMM + energy: tile 64x256, 2-stage ----------
#define FK_STAGE 51200
#define FK_FLT   102400
#define FK_SMEM  107776
__global__ void __launch_bounds__(256) fk_whenergy(const float* __restrict__ A,
        const __nv_bfloat16* __restrict__ Wh, const __nv_bfloat16* __restrict__ Wl,
        const float* __restrict__ coverage,
        const float* __restrict__ awc, const float* __restrict__ av) {
    extern __shared__ __align__(16) char sm[];
    uint32_t sb = smem_u32(sm);
    float* swsA = (float*)(sm + FK_FLT);
    float* swsB = (float*)(sm + FK_FLT + 1024);
    float* sawc = (float*)(sm + FK_FLT + 2048);
    float* sav  = (float*)(sm + FK_FLT + 3072);
    float* scov = (float*)(sm + FK_FLT + 4096);
    float* sred = (float*)(sm + FK_FLT + 4352);

    int tid = threadIdx.x, wid = tid >> 5, lane = tid & 31;
    int m0 = blockIdx.x * 64;
    int b0 = m0 / S;
    int b1 = (b0 + 1 < B) ? b0 + 1 : b0;
    int bswitch = (b0 + 1) * S - m0;
    int wr = (wid & 1) * 32, wc = (wid >> 1) * 64;
    int lr = lane & 7, sect = lane >> 3;
    uint32_t aoff = (uint32_t)((wr + (sect & 1)*8 + lr)*80 + (sect >> 1)*16);
    uint32_t boff = (uint32_t)((wc + (sect >> 1)*8 + lr)*80 + (sect & 1)*16);

    swsA[tid] = g_wsapp[b0*H + tid];
    swsB[tid] = g_wsapp[b1*H + tid];
    sawc[tid] = awc[tid];
    sav[tid]  = av[tid];
    if (tid < 64) scov[tid] = coverage[(size_t)m0 + tid];

    const char* wHs = (const char*)(Wh + (size_t)tid*E);
    const char* wLs = (const char*)(Wl + (size_t)tid*E);
    uint32_t wdoff = (uint32_t)(tid*80);
    int ar = tid >> 2, akb = (tid & 3) * 8;
    const float* aSrc = A + (size_t)(m0 + ar)*E + akb;

    float acc[2][8][4];
    #pragma unroll
    for (int i = 0; i < 2; i++)
        #pragma unroll
        for (int j = 0; j < 8; j++)
            #pragma unroll
            for (int e = 0; e < 4; e++) acc[i][j][e] = 0.f;

    #pragma unroll
    for (int i = 0; i < 4; i++) {
        cpa(sb + wdoff + i*16,         wHs + i*16);
        cpa(sb + 20480 + wdoff + i*16, wLs + i*16);
    }
    CP_COMMIT();
    float4 aN0 = *(const float4*)(aSrc);
    float4 aN1 = *(const float4*)(aSrc + 4);

    for (int c = 0; c < E/32; c++) {
        uint32_t st = sb + (uint32_t)((c & 1) * FK_STAGE);
        char* stc = sm + (c & 1) * FK_STAGE;
        st_hilo(stc + 40960, stc + 46080, ar, akb,     aN0);
        st_hilo(stc + 40960, stc + 46080, ar, akb + 4, aN1);
        if (c + 1 < E/32) {
            uint32_t st2 = sb + (uint32_t)(((c+1) & 1) * FK_STAGE);
            int ko = (c + 1) * 64;
            #pragma unroll
            for (int i = 0; i < 4; i++) {
                cpa(st2 + wdoff + i*16,         wHs + ko + i*16);
                cpa(st2 + 20480 + wdoff + i*16, wLs + ko + i*16);
            }
            CP_COMMIT();
            aN0 = *(const float4*)(aSrc + (c+1)*32);
            aN1 = *(const float4*)(aSrc + (c+1)*32 + 4);
            CP_WAIT1();
        } else CP_WAIT0();
        __syncthreads();
        #pragma unroll
        for (int ks = 0; ks < 64; ks += 32)
            mma_step(acc, st + 40960 + aoff + ks, st + 46080 + aoff + ks,
                          st + boff + ks,         st + 20480 + boff + ks);
        __syncthreads();
    }

    int gid = lane >> 2, t4 = lane & 3;
    #pragma unroll
    for (int mt = 0; mt < 2; mt++)
        #pragma unroll
        for (int eh = 0; eh < 2; eh++) {
            int row = wr + mt*16 + eh*8 + gid;
            float c = scov[row];
            const float* sws = (row < bswitch) ? swsA : swsB;
            float p = 0.f;
            #pragma unroll
            for (int nt = 0; nt < 8; nt++)
                #pragma unroll
                for (int e2 = 0; e2 < 2; e2++) {
                    int h = wc + nt*8 + 2*t4 + e2;
                    float x = acc[mt][nt][eh*2 + e2] + sws[h] + c * sawc[h];
                    p += tanhf(x) * sav[h];
                }
            p += __shfl_xor_sync(0xffffffffu, p, 1);
            p += __shfl_xor_sync(0xffffffffu, p, 2);
            if (t4 == 0) sred[row*4 + (wid >> 1)] = p;
        }
    __syncthreads();
    if (tid < 64)
        g_energy[(size_t)m0 + tid] = sred[tid*4] + sred[tid*4+1] + sred[tid*4+2] + sred[tid*4+3];
}

// ---------- LSTM + p_gen ----------
__global__ void k_lstm(const float* __restrict__ c0, const float* __restrict__ ws,
                       float* __restrict__ out) {
    int b = blockIdx.x, h = threadIdx.x;
    __shared__ float red[32];
    const float* g = g_gates + (size_t)b*G4;
    float ig = sigmoidf_(g[h]);
    float fg = sigmoidf_(g[H + h]);
    float gg = tanhf(g[2*H + h]);
    float og = sigmoidf_(g[3*H + h]);
    float c  = fg * c0[b*H + h] + ig * gg;
    float ht = og * tanhf(c);
    out[OUT_CT + (size_t)b*H + h] = c;
    out[OUT_HT + (size_t)b*H + h] = ht;
    split2(ht, &g_htH[b*H + h], &g_htL[b*H + h]);
    float hw = blk_sum(ht * ws[h], red);
    if (h == 0)
        g_pgen[b] = sigmoidf_(g_cwp[b] + g_cwp[B+b] + g_cwp[2*B+b] + g_cwp[3*B+b] + hw + g_exw[b]);
}

// ---------- vocab softmax: reduce partials, scale ----------
__global__ void k_rowsum() {
    int b = blockIdx.x, tid = threadIdx.x;
    __shared__ float red[32];
    float s = 0.f;
    for (int i = tid; i < NPX; i += 512) s += g_psum[(size_t)b*NPX + i];
    float t = blk_sum(s, red);
    if (tid == 0) g_rowinv[b] = 1.f / t;
}
__global__ void k_norm(float* __restrict__ out) {
    int b = blockIdx.y;
    int i = (blockIdx.x*blockDim.x + threadIdx.x) * 4;
    if (i < V) {
        float4* p = (float4*)(out + (size_t)b*V + i);
        float4 v = *p;
        float sc = g_pgen[b] * g_rowinv[b];
        v.x *= sc; v.y *= sc; v.z *= sc; v.w *= sc;
        *p = v;
    }
}

// ---------- attention softmax + coverage + loss partials + scatter (fused) ----------
__global__ void k_attn(const float* __restrict__ coverage, const int* __restrict__ enc_inputs,
                       float* __restrict__ out) {
    int b = blockIdx.x, tid = threadIdx.x;   // 512 threads
    __shared__ float red[32];
    __shared__ float sat[S];
    __shared__ int   sidx[S];
    float e = (tid < S) ? g_energy[b*S + tid] : -1e30f;
    float m = blk_max(e, red);
    float ex = (tid < S) ? expf(e - m) : 0.f;
    float sum = blk_sum(ex, red);
    float part = 0.f;
    if (tid < S) {
        float a = ex / sum;
        sat[tid] = a;
        sidx[tid] = enc_inputs[(size_t)b*S + tid];
        out[OUT_ATTN + (size_t)b*S + tid] = a;
        float c = coverage[(size_t)b*S + tid];
        out[OUT_COV + (size_t)b*S + tid] = c + a;
        part = fminf(a, c);
    }
    float ps = blk_sum(part, red);
    if (tid == 0) g_covpart[b] = ps;
    __syncthreads();
    if (tid < S) {
        int v = sidx[tid];
        bool win = true;
        for (int s2 = tid + 1; s2 < S; s2++)
            if (sidx[s2] == v) { win = false; break; }
        if (win) out[(size_t)b*V + v] += (1.f - g_pgen[b]) * sat[tid];
    }
}
__global__ void k_loss(float* __restrict__ out) {
    __shared__ float red[32];
    float s = blk_sum(g_covpart[threadIdx.x], red);
    if (threadIdx.x == 0) out[OUT_LOSS] = s;
}

// ---------- host ----------
extern "C" void kernel_launch(void* const* d_in, const int* in_sizes, int n_in,
                              void* d_out, int out_size) {
    const float* coverage   = (const float*)d_in[0];
    const float* enc_out    = (const float*)d_in[1];
    const float* h0         = (const float*)d_in[2];
    const float* c0         = (const float*)d_in[3];
    const float* attn       = (const float*)d_in[4];
    const int*   dec_input  = (const int*)d_in[5];
    const int*   enc_inputs = (const int*)d_in[6];
    const float* emb_table  = (const float*)d_in[7];
    const float* W_ih       = (const float*)d_in[8];
    const float* W_hh       = (const float*)d_in[9];
    const float* b_ih       = (const float*)d_in[10];
    const float* b_hh       = (const float*)d_in[11];
    const float* awh_W      = (const float*)d_in[12];
    const float* awh_b      = (const float*)d_in[13];
    const float* aws_W      = (const float*)d_in[14];
    const float* aws_b      = (const float*)d_in[15];
    const float* awc        = (const float*)d_in[16];
    const float* av         = (const float*)d_in[17];
    const float* wh         = (const float*)d_in[18];
    const float* ws         = (const float*)d_in[19];
    const float* wx         = (const float*)d_in[20];
    const float* v_W        = (const float*)d_in[21];
    const float* v_b        = (const float*)d_in[22];
    float* out = (float*)d_out;

    float *p_bcat, *p_gates, *p_wsapp, *p_bias2, *p_psum;
    __nv_bfloat16 *p_WcatH, *p_WcatL, *p_xcatH, *p_xcatL, *p_awhH, *p_awhL;
    __nv_bfloat16 *p_awsH, *p_awsL, *p_vWH, *p_vWL, *p_htH, *p_htL;
    cudaGetSymbolAddress((void**)&p_bcat,  g_bcat);
    cudaGetSymbolAddress((void**)&p_gates, g_gates);
    cudaGetSymbolAddress((void**)&p_wsapp, g_wsapp);
    cudaGetSymbolAddress((void**)&p_bias2, g_bias2);
    cudaGetSymbolAddress((void**)&p_psum,  g_psum);
    cudaGetSymbolAddress((void**)&p_WcatH, g_WcatH);
    cudaGetSymbolAddress((void**)&p_WcatL, g_WcatL);
    cudaGetSymbolAddress((void**)&p_xcatH, g_xcatH);
    cudaGetSymbolAddress((void**)&p_xcatL, g_xcatL);
    cudaGetSymbolAddress((void**)&p_awhH,  g_awhH);
    cudaGetSymbolAddress((void**)&p_awhL,  g_awhL);
    cudaGetSymbolAddress((void**)&p_awsH,  g_awsH);
    cudaGetSymbolAddress((void**)&p_awsL,  g_awsL);
    cudaGetSymbolAddress((void**)&p_vWH,   g_vWH);
    cudaGetSymbolAddress((void**)&p_vWL,   g_vWL);
    cudaGetSymbolAddress((void**)&p_htH,   g_htH);
    cudaGetSymbolAddress((void**)&p_htL,   g_htL);

    cudaFuncSetAttribute(fk_whenergy, cudaFuncAttributeMaxDynamicSharedMemorySize, FK_SMEM);
    cudaFuncSetAttribute(hgemm,       cudaFuncAttributeMaxDynamicSharedMemorySize, HG_SMEM);

    k_context<<<dim3(B, 4), 256>>>(attn, enc_out, dec_input, emb_table, wh, wx);
    k_packw<<<(G4*KX + 255)/256, 256>>>(W_ih, W_hh, b_ih, b_hh, aws_b, awh_b);
    k_cvt2<<<((H*E + H*H)/4 + 255)/256, 256>>>(awh_W, p_awhH, p_awhL, H*E,
                                               aws_W, p_awsH, p_awsL, H*H);
    k_cvt<<<(V*H/4 + 255)/256, 256>>>(v_W, p_vWH, p_vWL, V*H);
    k_packx<<<(B*KX + 255)/256, 256>>>(h0);
    hgemm<<<dim3(G4/128, B/128), 256, HG_SMEM>>>(p_xcatH, p_xcatL, p_WcatH, p_WcatL, p_bcat, p_gates, G4, KX, nullptr);
    k_lstm<<<B, 256>>>(c0, ws, out);
    hgemm<<<dim3(H/128, B/128), 256, HG_SMEM>>>(p_htH, p_htL, p_awsH, p_awsL, p_bias2, p_wsapp, H, H, nullptr);
    fk_whenergy<<<(B*S)/64, 256, FK_SMEM>>>(enc_out, p_awhH, p_awhL, coverage, awc, av);
    hgemm<<<dim3(NPX, B/128), 256, HG_SMEM>>>(p_htH, p_htL, p_vWH, p_vWL, v_b, out, V, H, p_psum);
    k_rowsum<<<B, 512>>>();
    k_norm<<<dim3((V/4 + 255)/256, B), 256>>>(out);
    k_attn<<<B, 512>>>(coverage, enc_inputs, out);
    k_loss<<<1, B>>>(out);
}

// round 12
// speedup vs baseline: 1.2339x; 1.0113x over previous
#include <cuda_runtime.h>
#include <cuda_bf16.h>
#include <math.h>
#include <stdint.h>

#define B 512
#define S 400
#define V 50000
#define E 512
#define H 256
#define EMB 128
#define KX (E + EMB + H)
#define G4 (4*H)
#define NPX ((V + 127) / 128)

#define OUT_COV    ((size_t)B*V)
#define OUT_HT     (OUT_COV  + (size_t)B*S)
#define OUT_CT     (OUT_HT   + (size_t)B*H)
#define OUT_ATTN   (OUT_CT   + (size_t)B*H)
#define OUT_LOSS   (OUT_ATTN + (size_t)B*S)

__device__ float g_ctxp[4][B*E];
__device__ float g_embed[B*EMB];
__device__ float g_bcat[G4];
__device__ float g_gates[B*G4];
__device__ float g_cwp[4*B];
__device__ float g_exw[B];
__device__ float g_pgen[B];
__device__ float g_wsapp[B*H];
__device__ float g_bias2[H];
__device__ float g_energy[B*S];
__device__ float g_covpart[B];
__device__ float g_rowinv[B];
__device__ float g_psum[(size_t)B*NPX];

__device__ __nv_bfloat16 g_WcatH[G4*KX], g_WcatL[G4*KX];
__device__ __nv_bfloat16 g_xcatH[B*KX],  g_xcatL[B*KX];
__device__ __nv_bfloat16 g_awhH[H*E],    g_awhL[H*E];
__device__ __nv_bfloat16 g_awsH[H*H],    g_awsL[H*H];
__device__ __nv_bfloat16 g_vWH[(size_t)V*H], g_vWL[(size_t)V*H];
__device__ __nv_bfloat16 g_htH[B*H],     g_htL[B*H];

// ---------- helpers ----------
__device__ __forceinline__ uint32_t smem_u32(const void* p) {
    uint32_t a;
    asm("{ .reg .u64 t; cvta.to.shared.u64 t, %1; cvt.u32.u64 %0, t; }" : "=r"(a) : "l"(p));
    return a;
}
__device__ __forceinline__ void ldm_x4(uint32_t* r, uint32_t addr) {
    asm volatile("ldmatrix.sync.aligned.m8n8.x4.shared.b16 {%0,%1,%2,%3}, [%4];"
        : "=r"(r[0]), "=r"(r[1]), "=r"(r[2]), "=r"(r[3]) : "r"(addr));
}
__device__ __forceinline__ void mma16816(float* d, const uint32_t* a, const uint32_t* b) {
    asm volatile("mma.sync.aligned.m16n8k16.row.col.f32.bf16.bf16.f32 "
        "{%0,%1,%2,%3}, {%4,%5,%6,%7}, {%8,%9}, {%0,%1,%2,%3};"
        : "+f"(d[0]), "+f"(d[1]), "+f"(d[2]), "+f"(d[3])
        : "r"(a[0]), "r"(a[1]), "r"(a[2]), "r"(a[3]), "r"(b[0]), "r"(b[1]));
}
__device__ __forceinline__ void cpa(uint32_t dst, const void* src) {
    asm volatile("cp.async.cg.shared.global [%0], [%1], 16;" :: "r"(dst), "l"(src));
}
__device__ __forceinline__ void cpa_z(uint32_t dst, const void* src, int sz) {
    asm volatile("cp.async.cg.shared.global [%0], [%1], 16, %2;" :: "r"(dst), "l"(src), "r"(sz));
}
#define CP_COMMIT() asm volatile("cp.async.commit_group;" ::: "memory")
#define CP_WAIT1()  asm volatile("cp.async.wait_group 1;" ::: "memory")
#define CP_WAIT0()  asm volatile("cp.async.wait_group 0;" ::: "memory")

__device__ __forceinline__ void st_hilo(char* hiB, char* loB, int row, int k, float4 v) {
    int off = row*80 + k*2;
    __nv_bfloat16 h0 = __float2bfloat16(v.x), h1 = __float2bfloat16(v.y),
                  h2 = __float2bfloat16(v.z), h3 = __float2bfloat16(v.w);
    __nv_bfloat16 l0 = __float2bfloat16(v.x - __bfloat162float(h0)),
                  l1 = __float2bfloat16(v.y - __bfloat162float(h1)),
                  l2 = __float2bfloat16(v.z - __bfloat162float(h2)),
                  l3 = __float2bfloat16(v.w - __bfloat162float(h3));
    *(__nv_bfloat162*)(hiB + off)     = __halves2bfloat162(h0, h1);
    *(__nv_bfloat162*)(hiB + off + 4) = __halves2bfloat162(h2, h3);
    *(__nv_bfloat162*)(loB + off)     = __halves2bfloat162(l0, l1);
    *(__nv_bfloat162*)(loB + off + 4) = __halves2bfloat162(l2, l3);
}
__device__ __forceinline__ void split2(float v, __nv_bfloat16* hp, __nv_bfloat16* lp) {
    __nv_bfloat16 h = __float2bfloat16(v);
    *hp = h;
    *lp = __float2bfloat16(v - __bfloat162float(h));
}
__device__ __forceinline__ void mma_step(float acc[2][8][4],
    uint32_t aHa, uint32_t aLa, uint32_t bHa, uint32_t bLa) {
    uint32_t aH[2][4], aL[2][4], bH[4][4], bL[4][4];
    #pragma unroll
    for (int mt = 0; mt < 2; mt++) { ldm_x4(aH[mt], aHa + mt*1280); ldm_x4(aL[mt], aLa + mt*1280); }
    #pragma unroll
    for (int np = 0; np < 4; np++) { ldm_x4(bH[np], bHa + np*1280); ldm_x4(bL[np], bLa + np*1280); }
    #pragma unroll
    for (int mt = 0; mt < 2; mt++)
        #pragma unroll
        for (int np = 0; np < 4; np++) {
            mma16816(acc[mt][2*np],   aH[mt], bH[np]);
            mma16816(acc[mt][2*np+1], aH[mt], bH[np]+2);
            mma16816(acc[mt][2*np],   aH[mt], bL[np]);
            mma16816(acc[mt][2*np+1], aH[mt], bL[np]+2);
            mma16816(acc[mt][2*np],   aL[mt], bH[np]);
            mma16816(acc[mt][2*np+1], aL[mt], bH[np]+2);
        }
}

__device__ __forceinline__ float sigmoidf_(float x) { return 1.f / (1.f + expf(-x)); }

__device__ __forceinline__ float blk_sum(float v, float* red) {
    int tid = threadIdx.x;
    #pragma unroll
    for (int o = 16; o; o >>= 1) v += __shfl_down_sync(0xffffffffu, v, o);
    if ((tid & 31) == 0) red[tid >> 5] = v;
    __syncthreads();
    float r;
    if (tid < 32) {
        int nw = (blockDim.x + 31) >> 5;
        r = (tid < nw) ? red[tid] : 0.f;
        #pragma unroll
        for (int o = 16; o; o >>= 1) r += __shfl_down_sync(0xffffffffu, r, o);
        if (tid == 0) red[0] = r;
    }
    __syncthreads();
    r = red[0];
    __syncthreads();
    return r;
}
__device__ __forceinline__ float blk_max(float v, float* red) {
    int tid = threadIdx.x;
    #pragma unroll
    for (int o = 16; o; o >>= 1) v = fmaxf(v, __shfl_down_sync(0xffffffffu, v, o));
    if ((tid & 31) == 0) red[tid >> 5] = v;
    __syncthreads();
    float r;
    if (tid < 32) {
        int nw = (blockDim.x + 31) >> 5;
        r = (tid < nw) ? red[tid] : -1e30f;
        #pragma unroll
        for (int o = 16; o; o >>= 1) r = fmaxf(r, __shfl_down_sync(0xffffffffu, r, o));
        if (tid == 0) red[0] = r;
    }
    __syncthreads();
    r = red[0];
    __syncthreads();
    return r;
}

// ---------- fp32 -> bf16 hi/lo converters ----------
__global__ void k_cvt(const float* __restrict__ src, __nv_bfloat16* __restrict__ hi,
                      __nv_bfloat16* __restrict__ lo, int n) {
    int idx = (blockIdx.x*blockDim.x + threadIdx.x) * 4;
    if (idx < n) {
        float4 v = *(const float4*)(src + idx);
        __nv_bfloat16 h0, h1, h2, h3, l0, l1, l2, l3;
        split2(v.x, &h0, &l0); split2(v.y, &h1, &l1);
        split2(v.z, &h2, &l2); split2(v.w, &h3, &l3);
        *(__nv_bfloat162*)(hi + idx)     = __halves2bfloat162(h0, h1);
        *(__nv_bfloat162*)(hi + idx + 2) = __halves2bfloat162(h2, h3);
        *(__nv_bfloat162*)(lo + idx)     = __halves2bfloat162(l0, l1);
        *(__nv_bfloat162*)(lo + idx + 2) = __halves2bfloat162(l2, l3);
    }
}
__global__ void k_cvt2(const float* __restrict__ sa, __nv_bfloat16* __restrict__ ah,
                       __nv_bfloat16* __restrict__ al, int na,
                       const float* __restrict__ sb2, __nv_bfloat16* __restrict__ bh,
                       __nv_bfloat16* __restrict__ bl, int nb) {
    int idx = (blockIdx.x*blockDim.x + threadIdx.x) * 4;
    const float* src; __nv_bfloat16 *hi, *lo;
    if (idx < na) { src = sa + idx; hi = ah + idx; lo = al + idx; }
    else {
        int j = idx - na;
        if (j >= nb) return;
        src = sb2 + j; hi = bh + j; lo = bl + j;
    }
    float4 v = *(const float4*)src;
    __nv_bfloat16 h0, h1, h2, h3, l0, l1, l2, l3;
    split2(v.x, &h0, &l0); split2(v.y, &h1, &l1);
    split2(v.z, &h2, &l2); split2(v.w, &h3, &l3);
    *(__nv_bfloat162*)(hi)     = __halves2bfloat162(h0, h1);
    *(__nv_bfloat162*)(hi + 2) = __halves2bfloat162(h2, h3);
    *(__nv_bfloat162*)(lo)     = __halves2bfloat162(l0, l1);
    *(__nv_bfloat162*)(lo + 2) = __halves2bfloat162(l2, l3);
}

// ---------- context: float4 loads, S-range split across thread halves ----------
__global__ void k_context(const float* __restrict__ attn, const float* __restrict__ enc_out,
                          const int* __restrict__ dec_input, const float* __restrict__ emb_table,
                          const float* __restrict__ wh, const float* __restrict__ wx) {
    int b = blockIdx.x, q = blockIdx.y, tid = threadIdx.x;
    int half = tid >> 7, lt = tid & 127;
    __shared__ float sa[2][S/8];
    __shared__ float sctx[E];
    __shared__ float red[32];
    int s0 = q * (S/4) + half * (S/8);
    for (int i = lt; i < S/8; i += 128) sa[half][i] = attn[(size_t)b*S + s0 + i];
    __syncthreads();
    const float* eb = enc_out + ((size_t)b*S + s0)*E;
    float4 acc = make_float4(0.f, 0.f, 0.f, 0.f);
    #pragma unroll 5
    for (int s = 0; s < S/8; s++) {
        float a = sa[half][s];
        float4 v = *(const float4*)(eb + (size_t)s*E + lt*4);
        acc.x += a*v.x; acc.y += a*v.y; acc.z += a*v.z; acc.w += a*v.w;
    }
    if (half == 0) *(float4*)(sctx + lt*4) = acc;
    __syncthreads();
    float cwp = 0.f;
    if (half == 1) {
        float4 o = *(const float4*)(sctx + lt*4);
        acc.x += o.x; acc.y += o.y; acc.z += o.z; acc.w += o.w;
        *(float4*)(&g_ctxp[q][b*E + lt*4]) = acc;
        cwp = acc.x*wh[lt*4] + acc.y*wh[lt*4+1] + acc.z*wh[lt*4+2] + acc.w*wh[lt*4+3];
    }
    float cw = blk_sum(cwp, red);
    if (tid == 0) g_cwp[q*B + b] = cw;
    if (q == 0) {
        float ew = 0.f;
        if (tid < EMB) {
            float e = emb_table[(size_t)dec_input[b]*EMB + tid];
            g_embed[b*EMB + tid] = e;
            ew = e * wx[tid];
        }
        float exw = blk_sum(ew, red);
        if (tid == 0) g_exw[b] = exw;
    }
}

__global__ void k_packw(const float* __restrict__ W_ih, const float* __restrict__ W_hh,
                        const float* __restrict__ b_ih, const float* __restrict__ b_hh,
                        const float* __restrict__ aws_b, const float* __restrict__ awh_b) {
    int idx = blockIdx.x*blockDim.x + threadIdx.x;
    if (idx < G4*KX) {
        int n = idx / KX, k = idx % KX;
        float w = (k < E+EMB) ? W_ih[(size_t)n*(E+EMB) + k] : W_hh[(size_t)n*H + (k - (E+EMB))];
        split2(w, &g_WcatH[idx], &g_WcatL[idx]);
    }
    if (idx < G4) g_bcat[idx] = b_ih[idx] + b_hh[idx];
    if (idx < H)  g_bias2[idx] = aws_b[idx] + awh_b[idx];
}
__global__ void k_packx(const float* __restrict__ h0) {
    int idx = blockIdx.x*blockDim.x + threadIdx.x;
    if (idx < B*KX) {
        int b = idx / KX, k = idx % KX;
        float v;
        if (k < E)          v = g_ctxp[0][b*E+k] + g_ctxp[1][b*E+k] + g_ctxp[2][b*E+k] + g_ctxp[3][b*E+k];
        else if (k < E+EMB) v = g_embed[b*EMB + (k - E)];
        else                v = h0[b*H + (k - E - EMB)];
        split2(v, &g_xcatH[idx], &g_xcatL[idx]);
    }
}

// ---------- HMMA GEMM, cp.async double-buffered: tile 128x128, K-chunk 32 ----------
#define HG_STAGE 40960
#define HG_SMEM  81920
__global__ void __launch_bounds__(256) hgemm(
        const __nv_bfloat16* __restrict__ Ah, const __nv_bfloat16* __restrict__ Al,
        const __nv_bfloat16* __restrict__ Wh, const __nv_bfloat16* __restrict__ Wl,
        const float* __restrict__ bias, float* __restrict__ C, int N, int K,
        float* __restrict__ psum) {
    extern __shared__ __align__(16) char sm[];
    uint32_t sb = smem_u32(sm);

    int tid = threadIdx.x, wid = tid >> 5, lane = tid & 31;
    int m0 = blockIdx.y * 128, n0 = blockIdx.x * 128;
    int wr = (wid & 3) * 32, wc = (wid >> 2) * 64;
    int lr = lane & 7, sect = lane >> 3;
    uint32_t aoff = (uint32_t)((wr + (sect & 1)*8 + lr)*80 + (sect >> 1)*16);
    uint32_t boff = (uint32_t)((wc + (sect >> 1)*8 + lr)*80 + (sect & 1)*16);

    int r = tid >> 1, kb = (tid & 1) * 16;
    uint32_t doff = (uint32_t)(r*80 + kb*2);
    const char* aHs = (const char*)(Ah + (size_t)(m0 + r)*K + kb);
    const char* aLs = (const char*)(Al + (size_t)(m0 + r)*K + kb);
    int n = n0 + r;
    int wsz = (n < N) ? 16 : 0;
    int nc = (n < N) ? n : 0;
    const char* wHs = (const char*)(Wh + (size_t)nc*K + kb);
    const char* wLs = (const char*)(Wl + (size_t)nc*K + kb);

    float acc[2][8][4];
    #pragma unroll
    for (int i = 0; i < 2; i++)
        #pragma unroll
        for (int j = 0; j < 8; j++)
            #pragma unroll
            for (int e = 0; e < 4; e++) acc[i][j][e] = 0.f;

    const int NC = K / 32;
    #pragma unroll
    for (int i = 0; i < 2; i++) {
        cpa(sb + doff + i*16,          aHs + i*16);
        cpa(sb + 10240 + doff + i*16,  aLs + i*16);
        cpa_z(sb + 20480 + doff + i*16, wHs + i*16, wsz);
        cpa_z(sb + 30720 + doff + i*16, wLs + i*16, wsz);
    }
    CP_COMMIT();

    for (int c = 0; c < NC; c++) {
        uint32_t st = sb + (uint32_t)((c & 1) * HG_STAGE);
        if (c + 1 < NC) {
            uint32_t st2 = sb + (uint32_t)(((c+1) & 1) * HG_STAGE);
            int ko = (c + 1) * 64;
            #pragma unroll
            for (int i = 0; i < 2; i++) {
                cpa(st2 + doff + i*16,          aHs + ko + i*16);
                cpa(st2 + 10240 + doff + i*16,  aLs + ko + i*16);
                cpa_z(st2 + 20480 + doff + i*16, wHs + ko + i*16, wsz);
                cpa_z(st2 + 30720 + doff + i*16, wLs + ko + i*16, wsz);
            }
            CP_COMMIT();
            CP_WAIT1();
        } else CP_WAIT0();
        __syncthreads();
        #pragma unroll
        for (int ks = 0; ks < 64; ks += 32)
            mma_step(acc, st + aoff + ks, st + 10240 + aoff + ks,
                          st + 20480 + boff + ks, st + 30720 + boff + ks);
        __syncthreads();
    }

    int gid = lane >> 2, t4 = lane & 3;
    if (psum == nullptr) {
        #pragma unroll
        for (int mt = 0; mt < 2; mt++)
            #pragma unroll
            for (int eh = 0; eh < 2; eh++) {
                size_t row = (size_t)(m0 + wr + mt*16 + eh*8 + gid);
                #pragma unroll
                for (int nt = 0; nt < 8; nt++) {
                    int col = n0 + wc + nt*8 + 2*t4;
                    if (col + 1 < N) {
                        float2 v;
                        v.x = acc[mt][nt][eh*2+0] + bias[col];
                        v.y = acc[mt][nt][eh*2+1] + bias[col+1];
                        *(float2*)&C[row*(size_t)N + col] = v;
                    } else if (col < N) {
                        C[row*(size_t)N + col] = acc[mt][nt][eh*2] + bias[col];
                    }
                }
            }
    } else {
        float* sp = (float*)sm;
        int cg = wid >> 2;
        #pragma unroll
        for (int mt = 0; mt < 2; mt++)
            #pragma unroll
            for (int eh = 0; eh < 2; eh++) {
                int rloc = wr + mt*16 + eh*8 + gid;
                size_t row = (size_t)(m0 + rloc);
                float p = 0.f;
                #pragma unroll
                for (int nt = 0; nt < 8; nt++) {
                    int col = n0 + wc + nt*8 + 2*t4;
                    if (col + 1 < N) {
                        float2 v;
                        v.x = expf(acc[mt][nt][eh*2+0] + bias[col]);
                        v.y = expf(acc[mt][nt][eh*2+1] + bias[col+1]);
                        *(float2*)&C[row*(size_t)N + col] = v;
                        p += v.x + v.y;
                    } else if (col < N) {
                        float v = expf(acc[mt][nt][eh*2] + bias[col]);
                        C[row*(size_t)N + col] = v;
                        p += v;
                    }
                }
                p += __shfl_xor_sync(0xffffffffu, p, 1);
                p += __shfl_xor_sync(0xffffffffu, p, 2);
                if (t4 == 0) sp[rloc*2 + cg] = p;
            }
        __syncthreads();
        if (tid < 128)
            psum[(size_t)(m0 + tid)*NPX + blockIdx.x] = sp[tid*2] + sp[tid*2+1];
    }
}

// ---------- fused wh_app GEMM + energy: tile 64x256, 2-stage ----------
#define FK_STAGE 51200
#define FK_FLT   102400
#define FK_SMEM  107776
__global__ void __launch_bounds__(256) fk_whenergy(const float* __restrict__ A,
        const __nv_bfloat16* __restrict__ Wh, const __nv_bfloat16* __restrict__ Wl,
        const float* __restrict__ coverage,
        const float* __restrict__ awc, const float* __restrict__ av) {
    extern __shared__ __align__(16) char sm[];
    uint32_t sb = smem_u32(sm);
    float* swsA = (float*)(sm + FK_FLT);
    float* swsB = (float*)(sm + FK_FLT + 1024);
    float* sawc = (float*)(sm + FK_FLT + 2048);
    float* sav  = (float*)(sm + FK_FLT + 3072);
    float* scov = (float*)(sm + FK_FLT + 4096);
    float* sred = (float*)(sm + FK_FLT + 4352);

    int tid = threadIdx.x, wid = tid >> 5, lane = tid & 31;
    int m0 = blockIdx.x * 64;
    int b0 = m0 / S;
    int b1 = (b0 + 1 < B) ? b0 + 1 : b0;
    int bswitch = (b0 + 1) * S - m0;
    int wr = (wid & 1) * 32, wc = (wid >> 1) * 64;
    int lr = lane & 7, sect = lane >> 3;
    uint32_t aoff = (uint32_t)((wr + (sect & 1)*8 + lr)*80 + (sect >> 1)*16);
    uint32_t boff = (uint32_t)((wc + (sect >> 1)*8 + lr)*80 + (sect & 1)*16);

    swsA[tid] = g_wsapp[b0*H + tid];
    swsB[tid] = g_wsapp[b1*H + tid];
    sawc[tid] = awc[tid];
    sav[tid]  = av[tid];
    if (tid < 64) scov[tid] = coverage[(size_t)m0 + tid];

    const char* wHs = (const char*)(Wh + (size_t)tid*E);
    const char* wLs = (const char*)(Wl + (size_t)tid*E);
    uint32_t wdoff = (uint32_t)(tid*80);
    int ar = tid >> 2, akb = (tid & 3) * 8;
    const float* aSrc = A + (size_t)(m0 + ar)*E + akb;

    float acc[2][8][4];
    #pragma unroll
    for (int i = 0; i < 2; i++)
        #pragma unroll
        for (int j = 0; j < 8; j++)
            #pragma unroll
            for (int e = 0; e < 4; e++) acc[i][j][e] = 0.f;

    #pragma unroll
    for (int i = 0; i < 4; i++) {
        cpa(sb + wdoff + i*16,         wHs + i*16);
        cpa(sb + 20480 + wdoff + i*16, wLs + i*16);
    }
    CP_COMMIT();
    float4 aN0 = *(const float4*)(aSrc);
    float4 aN1 = *(const float4*)(aSrc + 4);

    for (int c = 0; c < E/32; c++) {
        uint32_t st = sb + (uint32_t)((c & 1) * FK_STAGE);
        char* stc = sm + (c & 1) * FK_STAGE;
        st_hilo(stc + 40960, stc + 46080, ar, akb,     aN0);
        st_hilo(stc + 40960, stc + 46080, ar, akb + 4, aN1);
        if (c + 1 < E/32) {
            uint32_t st2 = sb + (uint32_t)(((c+1) & 1) * FK_STAGE);
            int ko = (c + 1) * 64;
            #pragma unroll
            for (int i = 0; i < 4; i++) {
                cpa(st2 + wdoff + i*16,         wHs + ko + i*16);
                cpa(st2 + 20480 + wdoff + i*16, wLs + ko + i*16);
            }
            CP_COMMIT();
            aN0 = *(const float4*)(aSrc + (c+1)*32);
            aN1 = *(const float4*)(aSrc + (c+1)*32 + 4);
            CP_WAIT1();
        } else CP_WAIT0();
        __syncthreads();
        #pragma unroll
        for (int ks = 0; ks < 64; ks += 32)
            mma_step(acc, st + 40960 + aoff + ks, st + 46080 + aoff + ks,
                          st + boff + ks,         st + 20480 + boff + ks);
        __syncthreads();
    }

    int gid = lane >> 2, t4 = lane & 3;
    #pragma unroll
    for (int mt = 0; mt < 2; mt++)
        #pragma unroll
        for (int eh = 0; eh < 2; eh++) {
            int row = wr + mt*16 + eh*8 + gid;
            float c = scov[row];
            const float* sws = (row < bswitch) ? swsA : swsB;
            float p = 0.f;
            #pragma unroll
            for (int nt = 0; nt < 8; nt++)
                #pragma unroll
                for (int e2 = 0; e2 < 2; e2++) {
                    int h = wc + nt*8 + 2*t4 + e2;
                    float x = acc[mt][nt][eh*2 + e2] + sws[h] + c * sawc[h];
                    p += tanhf(x) * sav[h];
                }
            p += __shfl_xor_sync(0xffffffffu, p, 1);
            p += __shfl_xor_sync(0xffffffffu, p, 2);
            if (t4 == 0) sred[row*4 + (wid >> 1)] = p;
        }
    __syncthreads();
    if (tid < 64)
        g_energy[(size_t)m0 + tid] = sred[tid*4] + sred[tid*4+1] + sred[tid*4+2] + sred[tid*4+3];
}

// ---------- LSTM + p_gen ----------
__global__ void k_lstm(const float* __restrict__ c0, const float* __restrict__ ws,
                       float* __restrict__ out) {
    int b = blockIdx.x, h = threadIdx.x;
    __shared__ float red[32];
    const float* g = g_gates + (size_t)b*G4;
    float ig = sigmoidf_(g[h]);
    float fg = sigmoidf_(g[H + h]);
    float gg = tanhf(g[2*H + h]);
    float og = sigmoidf_(g[3*H + h]);
    float c  = fg * c0[b*H + h] + ig * gg;
    float ht = og * tanhf(c);
    out[OUT_CT + (size_t)b*H + h] = c;
    out[OUT_HT + (size_t)b*H + h] = ht;
    split2(ht, &g_htH[b*H + h], &g_htL[b*H + h]);
    float hw = blk_sum(ht * ws[h], red);
    if (h == 0)
        g_pgen[b] = sigmoidf_(g_cwp[b] + g_cwp[B+b] + g_cwp[2*B+b] + g_cwp[3*B+b] + hw + g_exw[b]);
}

// ---------- vocab softmax: reduce partials, scale ----------
__global__ void k_rowsum() {
    int b = blockIdx.x, tid = threadIdx.x;
    __shared__ float red[32];
    float s = 0.f;
    for (int i = tid; i < NPX; i += 512) s += g_psum[(size_t)b*NPX + i];
    float t = blk_sum(s, red);
    if (tid == 0) g_rowinv[b] = 1.f / t;
}
__global__ void k_norm(float* __restrict__ out) {
    int b = blockIdx.y;
    int i = (blockIdx.x*blockDim.x + threadIdx.x) * 4;
    if (i < V) {
        float4* p = (float4*)(out + (size_t)b*V + i);
        float4 v = *p;
        float sc = g_pgen[b] * g_rowinv[b];
        v.x *= sc; v.y *= sc; v.z *= sc; v.w *= sc;
        *p = v;
    }
}

// ---------- attention softmax + coverage + loss partials (NO scatter) ----------
__global__ void k_attnA(const float* __restrict__ coverage, float* __restrict__ out) {
    int b = blockIdx.x, tid = threadIdx.x;
    __shared__ float red[32];
    float e = (tid < S) ? g_energy[b*S + tid] : -1e30f;
    float m = blk_max(e, red);
    float ex = (tid < S) ? expf(e - m) : 0.f;
    float sum = blk_sum(ex, red);
    float part = 0.f;
    if (tid < S) {
        float a = ex / sum;
        out[OUT_ATTN + (size_t)b*S + tid] = a;
        float c = coverage[(size_t)b*S + tid];
        out[OUT_COV + (size_t)b*S + tid] = c + a;
        part = fminf(a, c);
    }
    float ps = blk_sum(part, red);
    if (tid == 0) g_covpart[b] = ps;
}
__global__ void k_loss(float* __restrict__ out) {
    __shared__ float red[32];
    float s = blk_sum(g_covpart[threadIdx.x], red);
    if (threadIdx.x == 0) out[OUT_LOSS] = s;
}
// ---------- scatter (last-s-wins), after k_norm ----------
__global__ void k_scat(const int* __restrict__ enc_inputs, float* __restrict__ out) {
    int b = blockIdx.x, tid = threadIdx.x;
    __shared__ int   sidx[S];
    __shared__ float sat[S];
    if (tid < S) {
        sidx[tid] = enc_inputs[(size_t)b*S + tid];
        sat[tid]  = out[OUT_ATTN + (size_t)b*S + tid];
    }
    __syncthreads();
    if (tid < S) {
        int v = sidx[tid];
        bool win = true;
        for (int s2 = tid + 1; s2 < S; s2++)
            if (sidx[s2] == v) { win = false; break; }
        if (win) out[(size_t)b*V + v] += (1.f - g_pgen[b]) * sat[tid];
    }
}

// ---------- host ----------
extern "C" void kernel_launch(void* const* d_in, const int* in_sizes, int n_in,
                              void* d_out, int out_size) {
    const float* coverage   = (const float*)d_in[0];
    const float* enc_out    = (const float*)d_in[1];
    const float* h0         = (const float*)d_in[2];
    const float* c0         = (const float*)d_in[3];
    const float* attn       = (const float*)d_in[4];
    const int*   dec_input  = (const int*)d_in[5];
    const int*   enc_inputs = (const int*)d_in[6];
    const float* emb_table  = (const float*)d_in[7];
    const float* W_ih       = (const float*)d_in[8];
    const float* W_hh       = (const float*)d_in[9];
    const float* b_ih       = (const float*)d_in[10];
    const float* b_hh       = (const float*)d_in[11];
    const float* awh_W      = (const float*)d_in[12];
    const float* awh_b      = (const float*)d_in[13];
    const float* aws_W      = (const float*)d_in[14];
    const float* aws_b      = (const float*)d_in[15];
    const float* awc        = (const float*)d_in[16];
    const float* av         = (const float*)d_in[17];
    const float* wh         = (const float*)d_in[18];
    const float* ws         = (const float*)d_in[19];
    const float* wx         = (const float*)d_in[20];
    const float* v_W        = (const float*)d_in[21];
    const float* v_b        = (const float*)d_in[22];
    float* out = (float*)d_out;

    float *p_bcat, *p_gates, *p_wsapp, *p_bias2, *p_psum;
    __nv_bfloat16 *p_WcatH, *p_WcatL, *p_xcatH, *p_xcatL, *p_awhH, *p_awhL;
    __nv_bfloat16 *p_awsH, *p_awsL, *p_vWH, *p_vWL, *p_htH, *p_htL;
    cudaGetSymbolAddress((void**)&p_bcat,  g_bcat);
    cudaGetSymbolAddress((void**)&p_gates, g_gates);
    cudaGetSymbolAddress((void**)&p_wsapp, g_wsapp);
    cudaGetSymbolAddress((void**)&p_bias2, g_bias2);
    cudaGetSymbolAddress((void**)&p_psum,  g_psum);
    cudaGetSymbolAddress((void**)&p_WcatH, g_WcatH);
    cudaGetSymbolAddress((void**)&p_WcatL, g_WcatL);
    cudaGetSymbolAddress((void**)&p_xcatH, g_xcatH);
    cudaGetSymbolAddress((void**)&p_xcatL, g_xcatL);
    cudaGetSymbolAddress((void**)&p_awhH,  g_awhH);
    cudaGetSymbolAddress((void**)&p_awhL,  g_awhL);
    cudaGetSymbolAddress((void**)&p_awsH,  g_awsH);
    cudaGetSymbolAddress((void**)&p_awsL,  g_awsL);
    cudaGetSymbolAddress((void**)&p_vWH,   g_vWH);
    cudaGetSymbolAddress((void**)&p_vWL,   g_vWL);
    cudaGetSymbolAddress((void**)&p_htH,   g_htH);
    cudaGetSymbolAddress((void**)&p_htL,   g_htL);

    cudaFuncSetAttribute(fk_whenergy, cudaFuncAttributeMaxDynamicSharedMemorySize, FK_SMEM);
    cudaFuncSetAttribute(hgemm,       cudaFuncAttributeMaxDynamicSharedMemorySize, HG_SMEM);

    // one-time side stream + events (host-side objects only; no device memory)
    static cudaStream_t s2 = nullptr;
    static cudaEvent_t evA = nullptr, evB = nullptr, evC = nullptr, evD = nullptr;
    if (s2 == nullptr) {
        cudaStreamCreateWithFlags(&s2, cudaStreamNonBlocking);
        cudaEventCreateWithFlags(&evA, cudaEventDisableTiming);
        cudaEventCreateWithFlags(&evB, cudaEventDisableTiming);
        cudaEventCreateWithFlags(&evC, cudaEventDisableTiming);
        cudaEventCreateWithFlags(&evD, cudaEventDisableTiming);
    }

    // fork: prep work (weights) on s2, hidden under context on main stream
    cudaEventRecord(evA, 0);
    cudaStreamWaitEvent(s2, evA, 0);
    k_packw<<<(G4*KX + 255)/256, 256, 0, s2>>>(W_ih, W_hh, b_ih, b_hh, aws_b, awh_b);
    k_cvt2<<<((H*E + H*H)/4 + 255)/256, 256, 0, s2>>>(awh_W, p_awhH, p_awhL, H*E,
                                                      aws_W, p_awsH, p_awsL, H*H);
    k_cvt<<<(V*H/4 + 255)/256, 256, 0, s2>>>(v_W, p_vWH, p_vWL, V*H);
    cudaEventRecord(evB, s2);

    k_context<<<dim3(B, 4), 256>>>(attn, enc_out, dec_input, emb_table, wh, wx);
    k_packx<<<(B*KX + 255)/256, 256>>>(h0);
    cudaStreamWaitEvent(0, evB, 0);   // join: Wcat/aws/awh/vW ready
    hgemm<<<dim3(G4/128, B/128), 256, HG_SMEM>>>(p_xcatH, p_xcatL, p_WcatH, p_WcatL, p_bcat, p_gates, G4, KX, nullptr);
    k_lstm<<<B, 256>>>(c0, ws, out);
    hgemm<<<dim3(H/128, B/128), 256, HG_SMEM>>>(p_htH, p_htL, p_awsH, p_awsL, p_bias2, p_wsapp, H, H, nullptr);
    fk_whenergy<<<(B*S)/64, 256, FK_SMEM>>>(enc_out, p_awhH, p_awhL, coverage, awc, av);

    // fork: attention softmax/coverage/loss on s2, hidden under logits chain
    cudaEventRecord(evC, 0);
    cudaStreamWaitEvent(s2, evC, 0);
    k_attnA<<<B, 512, 0, s2>>>(coverage, out);
    k_loss<<<1, B, 0, s2>>>(out);
    cudaEventRecord(evD, s2);

    hgemm<<<dim3(NPX, B/128), 256, HG_SMEM>>>(p_htH, p_htL, p_vWH, p_vWL, v_b, out, V, H, p_psum);
    k_rowsum<<<B, 512>>>();
    k_norm<<<dim3((V/4 + 255)/256, B), 256>>>(out);
    cudaStreamWaitEvent(0, evD, 0);   // join: attn probs + pgen consumers done
    k_scat<<<B, 512>>>(enc_inputs, out);
}

// round 13
// speedup vs baseline: 1.3041x; 1.0569x over previous
#include <cuda_runtime.h>
#include <cuda_bf16.h>
#include <math.h>
#include <stdint.h>

#define B 512
#define S 400
#define V 50000
#define E 512
#define H 256
#define EMB 128
#define KX (E + EMB + H)
#define G4 (4*H)
#define NPX ((V + 127) / 128)

#define OUT_COV    ((size_t)B*V)
#define OUT_HT     (OUT_COV  + (size_t)B*S)
#define OUT_CT     (OUT_HT   + (size_t)B*H)
#define OUT_ATTN   (OUT_CT   + (size_t)B*H)
#define OUT_LOSS   (OUT_ATTN + (size_t)B*S)

__device__ float g_ctxp[4][B*E];
__device__ float g_embed[B*EMB];
__device__ float g_bcat[G4];
__device__ float g_gates[B*G4];
__device__ float g_cwp[4*B];
__device__ float g_exw[B];
__device__ float g_pgen[B];
__device__ float g_wsapp[B*H];
__device__ float g_bias2[H];
__device__ float g_energy[B*S];
__device__ float g_covpart[B];
__device__ float g_rowinv[B];
__device__ float g_psum[(size_t)B*NPX];

__device__ __nv_bfloat16 g_WcatH[G4*KX], g_WcatL[G4*KX];
__device__ __nv_bfloat16 g_xcatH[B*KX],  g_xcatL[B*KX];
__device__ __nv_bfloat16 g_awhH[H*E],    g_awhL[H*E];
__device__ __nv_bfloat16 g_awsH[H*H],    g_awsL[H*H];
__device__ __nv_bfloat16 g_vWH[(size_t)V*H], g_vWL[(size_t)V*H];
__device__ __nv_bfloat16 g_htH[B*H],     g_htL[B*H];

// ---------- helpers ----------
__device__ __forceinline__ uint32_t smem_u32(const void* p) {
    uint32_t a;
    asm("{ .reg .u64 t; cvta.to.shared.u64 t, %1; cvt.u32.u64 %0, t; }" : "=r"(a) : "l"(p));
    return a;
}
__device__ __forceinline__ void ldm_x4(uint32_t* r, uint32_t addr) {
    asm volatile("ldmatrix.sync.aligned.m8n8.x4.shared.b16 {%0,%1,%2,%3}, [%4];"
        : "=r"(r[0]), "=r"(r[1]), "=r"(r[2]), "=r"(r[3]) : "r"(addr));
}
__device__ __forceinline__ void mma16816(float* d, const uint32_t* a, const uint32_t* b) {
    asm volatile("mma.sync.aligned.m16n8k16.row.col.f32.bf16.bf16.f32 "
        "{%0,%1,%2,%3}, {%4,%5,%6,%7}, {%8,%9}, {%0,%1,%2,%3};"
        : "+f"(d[0]), "+f"(d[1]), "+f"(d[2]), "+f"(d[3])
        : "r"(a[0]), "r"(a[1]), "r"(a[2]), "r"(a[3]), "r"(b[0]), "r"(b[1]));
}
__device__ __forceinline__ void cpa(uint32_t dst, const void* src) {
    asm volatile("cp.async.cg.shared.global [%0], [%1], 16;" :: "r"(dst), "l"(src));
}
__device__ __forceinline__ void cpa_z(uint32_t dst, const void* src, int sz) {
    asm volatile("cp.async.cg.shared.global [%0], [%1], 16, %2;" :: "r"(dst), "l"(src), "r"(sz));
}
#define CP_COMMIT() asm volatile("cp.async.commit_group;" ::: "memory")
#define CP_WAIT1()  asm volatile("cp.async.wait_group 1;" ::: "memory")
#define CP_WAIT0()  asm volatile("cp.async.wait_group 0;" ::: "memory")

__device__ __forceinline__ void st_hilo(char* hiB, char* loB, int row, int k, float4 v) {
    int off = row*80 + k*2;
    __nv_bfloat16 h0 = __float2bfloat16(v.x), h1 = __float2bfloat16(v.y),
                  h2 = __float2bfloat16(v.z), h3 = __float2bfloat16(v.w);
    __nv_bfloat16 l0 = __float2bfloat16(v.x - __bfloat162float(h0)),
                  l1 = __float2bfloat16(v.y - __bfloat162float(h1)),
                  l2 = __float2bfloat16(v.z - __bfloat162float(h2)),
                  l3 = __float2bfloat16(v.w - __bfloat162float(h3));
    *(__nv_bfloat162*)(hiB + off)     = __halves2bfloat162(h0, h1);
    *(__nv_bfloat162*)(hiB + off + 4) = __halves2bfloat162(h2, h3);
    *(__nv_bfloat162*)(loB + off)     = __halves2bfloat162(l0, l1);
    *(__nv_bfloat162*)(loB + off + 4) = __halves2bfloat162(l2, l3);
}
__device__ __forceinline__ void split2(float v, __nv_bfloat16* hp, __nv_bfloat16* lp) {
    __nv_bfloat16 h = __float2bfloat16(v);
    *hp = h;
    *lp = __float2bfloat16(v - __bfloat162float(h));
}
__device__ __forceinline__ void mma_step(float acc[2][8][4],
    uint32_t aHa, uint32_t aLa, uint32_t bHa, uint32_t bLa) {
    uint32_t aH[2][4], aL[2][4], bH[4][4], bL[4][4];
    #pragma unroll
    for (int mt = 0; mt < 2; mt++) { ldm_x4(aH[mt], aHa + mt*1280); ldm_x4(aL[mt], aLa + mt*1280); }
    #pragma unroll
    for (int np = 0; np < 4; np++) { ldm_x4(bH[np], bHa + np*1280); ldm_x4(bL[np], bLa + np*1280); }
    #pragma unroll
    for (int mt = 0; mt < 2; mt++)
        #pragma unroll
        for (int np = 0; np < 4; np++) {
            mma16816(acc[mt][2*np],   aH[mt], bH[np]);
            mma16816(acc[mt][2*np+1], aH[mt], bH[np]+2);
            mma16816(acc[mt][2*np],   aH[mt], bL[np]);
            mma16816(acc[mt][2*np+1], aH[mt], bL[np]+2);
            mma16816(acc[mt][2*np],   aL[mt], bH[np]);
            mma16816(acc[mt][2*np+1], aL[mt], bH[np]+2);
        }
}

__device__ __forceinline__ float sigmoidf_(float x) { return 1.f / (1.f + expf(-x)); }

__device__ __forceinline__ float blk_sum(float v, float* red) {
    int tid = threadIdx.x;
    #pragma unroll
    for (int o = 16; o; o >>= 1) v += __shfl_down_sync(0xffffffffu, v, o);
    if ((tid & 31) == 0) red[tid >> 5] = v;
    __syncthreads();
    float r;
    if (tid < 32) {
        int nw = (blockDim.x + 31) >> 5;
        r = (tid < nw) ? red[tid] : 0.f;
        #pragma unroll
        for (int o = 16; o; o >>= 1) r += __shfl_down_sync(0xffffffffu, r, o);
        if (tid == 0) red[0] = r;
    }
    __syncthreads();
    r = red[0];
    __syncthreads();
    return r;
}
__device__ __forceinline__ float blk_max(float v, float* red) {
    int tid = threadIdx.x;
    #pragma unroll
    for (int o = 16; o; o >>= 1) v = fmaxf(v, __shfl_down_sync(0xffffffffu, v, o));
    if ((tid & 31) == 0) red[tid >> 5] = v;
    __syncthreads();
    float r;
    if (tid < 32) {
        int nw = (blockDim.x + 31) >> 5;
        r = (tid < nw) ? red[tid] : -1e30f;
        #pragma unroll
        for (int o = 16; o; o >>= 1) r = fmaxf(r, __shfl_down_sync(0xffffffffu, r, o));
        if (tid == 0) red[0] = r;
    }
    __syncthreads();
    r = red[0];
    __syncthreads();
    return r;
}

// ---------- fp32 -> bf16 hi/lo converters ----------
__global__ void k_cvt(const float* __restrict__ src, __nv_bfloat16* __restrict__ hi,
                      __nv_bfloat16* __restrict__ lo, int n) {
    int idx = (blockIdx.x*blockDim.x + threadIdx.x) * 4;
    if (idx < n) {
        float4 v = *(const float4*)(src + idx);
        __nv_bfloat16 h0, h1, h2, h3, l0, l1, l2, l3;
        split2(v.x, &h0, &l0); split2(v.y, &h1, &l1);
        split2(v.z, &h2, &l2); split2(v.w, &h3, &l3);
        *(__nv_bfloat162*)(hi + idx)     = __halves2bfloat162(h0, h1);
        *(__nv_bfloat162*)(hi + idx + 2) = __halves2bfloat162(h2, h3);
        *(__nv_bfloat162*)(lo + idx)     = __halves2bfloat162(l0, l1);
        *(__nv_bfloat162*)(lo + idx + 2) = __halves2bfloat162(l2, l3);
    }
}
__global__ void k_cvt2(const float* __restrict__ sa, __nv_bfloat16* __restrict__ ah,
                       __nv_bfloat16* __restrict__ al, int na,
                       const float* __restrict__ sb2, __nv_bfloat16* __restrict__ bh,
                       __nv_bfloat16* __restrict__ bl, int nb) {
    int idx = (blockIdx.x*blockDim.x + threadIdx.x) * 4;
    const float* src; __nv_bfloat16 *hi, *lo;
    if (idx < na) { src = sa + idx; hi = ah + idx; lo = al + idx; }
    else {
        int j = idx - na;
        if (j >= nb) return;
        src = sb2 + j; hi = bh + j; lo = bl + j;
    }
    float4 v = *(const float4*)src;
    __nv_bfloat16 h0, h1, h2, h3, l0, l1, l2, l3;
    split2(v.x, &h0, &l0); split2(v.y, &h1, &l1);
    split2(v.z, &h2, &l2); split2(v.w, &h3, &l3);
    *(__nv_bfloat162*)(hi)     = __halves2bfloat162(h0, h1);
    *(__nv_bfloat162*)(hi + 2) = __halves2bfloat162(h2, h3);
    *(__nv_bfloat162*)(lo)     = __halves2bfloat162(l0, l1);
    *(__nv_bfloat162*)(lo + 2) = __halves2bfloat162(l2, l3);
}

// ---------- context ----------
__global__ void k_context(const float* __restrict__ attn, const float* __restrict__ enc_out,
                          const int* __restrict__ dec_input, const float* __restrict__ emb_table,
                          const float* __restrict__ wh, const float* __restrict__ wx) {
    int b = blockIdx.x, q = blockIdx.y, tid = threadIdx.x;
    int half = tid >> 7, lt = tid & 127;
    __shared__ float sa[2][S/8];
    __shared__ float sctx[E];
    __shared__ float red[32];
    int s0 = q * (S/4) + half * (S/8);
    for (int i = lt; i < S/8; i += 128) sa[half][i] = attn[(size_t)b*S + s0 + i];
    __syncthreads();
    const float* eb = enc_out + ((size_t)b*S + s0)*E;
    float4 acc = make_float4(0.f, 0.f, 0.f, 0.f);
    #pragma unroll 5
    for (int s = 0; s < S/8; s++) {
        float a = sa[half][s];
        float4 v = *(const float4*)(eb + (size_t)s*E + lt*4);
        acc.x += a*v.x; acc.y += a*v.y; acc.z += a*v.z; acc.w += a*v.w;
    }
    if (half == 0) *(float4*)(sctx + lt*4) = acc;
    __syncthreads();
    float cwp = 0.f;
    if (half == 1) {
        float4 o = *(const float4*)(sctx + lt*4);
        acc.x += o.x; acc.y += o.y; acc.z += o.z; acc.w += o.w;
        *(float4*)(&g_ctxp[q][b*E + lt*4]) = acc;
        cwp = acc.x*wh[lt*4] + acc.y*wh[lt*4+1] + acc.z*wh[lt*4+2] + acc.w*wh[lt*4+3];
    }
    float cw = blk_sum(cwp, red);
    if (tid == 0) g_cwp[q*B + b] = cw;
    if (q == 0) {
        float ew = 0.f;
        if (tid < EMB) {
            float e = emb_table[(size_t)dec_input[b]*EMB + tid];
            g_embed[b*EMB + tid] = e;
            ew = e * wx[tid];
        }
        float exw = blk_sum(ew, red);
        if (tid == 0) g_exw[b] = exw;
    }
}

__global__ void k_packw(const float* __restrict__ W_ih, const float* __restrict__ W_hh,
                        const float* __restrict__ b_ih, const float* __restrict__ b_hh,
                        const float* __restrict__ aws_b, const float* __restrict__ awh_b) {
    int idx = blockIdx.x*blockDim.x + threadIdx.x;
    if (idx < G4*KX) {
        int n = idx / KX, k = idx % KX;
        float w = (k < E+EMB) ? W_ih[(size_t)n*(E+EMB) + k] : W_hh[(size_t)n*H + (k - (E+EMB))];
        split2(w, &g_WcatH[idx], &g_WcatL[idx]);
    }
    if (idx < G4) g_bcat[idx] = b_ih[idx] + b_hh[idx];
    if (idx < H)  g_bias2[idx] = aws_b[idx] + awh_b[idx];
}
__global__ void k_packx(const float* __restrict__ h0) {
    int idx = blockIdx.x*blockDim.x + threadIdx.x;
    if (idx < B*KX) {
        int b = idx / KX, k = idx % KX;
        float v;
        if (k < E)          v = g_ctxp[0][b*E+k] + g_ctxp[1][b*E+k] + g_ctxp[2][b*E+k] + g_ctxp[3][b*E+k];
        else if (k < E+EMB) v = g_embed[b*EMB + (k - E)];
        else                v = h0[b*H + (k - E - EMB)];
        split2(v, &g_xcatH[idx], &g_xcatL[idx]);
    }
}

// ---------- HMMA GEMM, cp.async double-buffered ----------
#define HG_STAGE 40960
#define HG_SMEM  81920
__global__ void __launch_bounds__(256) hgemm(
        const __nv_bfloat16* __restrict__ Ah, const __nv_bfloat16* __restrict__ Al,
        const __nv_bfloat16* __restrict__ Wh, const __nv_bfloat16* __restrict__ Wl,
        const float* __restrict__ bias, float* __restrict__ C, int N, int K,
        float* __restrict__ psum) {
    extern __shared__ __align__(16) char sm[];
    uint32_t sb = smem_u32(sm);

    int tid = threadIdx.x, wid = tid >> 5, lane = tid & 31;
    int m0 = blockIdx.y * 128, n0 = blockIdx.x * 128;
    int wr = (wid & 3) * 32, wc = (wid >> 2) * 64;
    int lr = lane & 7, sect = lane >> 3;
    uint32_t aoff = (uint32_t)((wr + (sect & 1)*8 + lr)*80 + (sect >> 1)*16);
    uint32_t boff = (uint32_t)((wc + (sect >> 1)*8 + lr)*80 + (sect & 1)*16);

    int r = tid >> 1, kb = (tid & 1) * 16;
    uint32_t doff = (uint32_t)(r*80 + kb*2);
    const char* aHs = (const char*)(Ah + (size_t)(m0 + r)*K + kb);
    const char* aLs = (const char*)(Al + (size_t)(m0 + r)*K + kb);
    int n = n0 + r;
    int wsz = (n < N) ? 16 : 0;
    int nc = (n < N) ? n : 0;
    const char* wHs = (const char*)(Wh + (size_t)nc*K + kb);
    const char* wLs = (const char*)(Wl + (size_t)nc*K + kb);

    float acc[2][8][4];
    #pragma unroll
    for (int i = 0; i < 2; i++)
        #pragma unroll
        for (int j = 0; j < 8; j++)
            #pragma unroll
            for (int e = 0; e < 4; e++) acc[i][j][e] = 0.f;

    const int NC = K / 32;
    #pragma unroll
    for (int i = 0; i < 2; i++) {
        cpa(sb + doff + i*16,          aHs + i*16);
        cpa(sb + 10240 + doff + i*16,  aLs + i*16);
        cpa_z(sb + 20480 + doff + i*16, wHs + i*16, wsz);
        cpa_z(sb + 30720 + doff + i*16, wLs + i*16, wsz);
    }
    CP_COMMIT();

    for (int c = 0; c < NC; c++) {
        uint32_t st = sb + (uint32_t)((c & 1) * HG_STAGE);
        if (c + 1 < NC) {
            uint32_t st2 = sb + (uint32_t)(((c+1) & 1) * HG_STAGE);
            int ko = (c + 1) * 64;
            #pragma unroll
            for (int i = 0; i < 2; i++) {
                cpa(st2 + doff + i*16,          aHs + ko + i*16);
                cpa(st2 + 10240 + doff + i*16,  aLs + ko + i*16);
                cpa_z(st2 + 20480 + doff + i*16, wHs + ko + i*16, wsz);
                cpa_z(st2 + 30720 + doff + i*16, wLs + ko + i*16, wsz);
            }
            CP_COMMIT();
            CP_WAIT1();
        } else CP_WAIT0();
        __syncthreads();
        #pragma unroll
        for (int ks = 0; ks < 64; ks += 32)
            mma_step(acc, st + aoff + ks, st + 10240 + aoff + ks,
                          st + 20480 + boff + ks, st + 30720 + boff + ks);
        __syncthreads();
    }

    int gid = lane >> 2, t4 = lane & 3;
    if (psum == nullptr) {
        #pragma unroll
        for (int mt = 0; mt < 2; mt++)
            #pragma unroll
            for (int eh = 0; eh < 2; eh++) {
                size_t row = (size_t)(m0 + wr + mt*16 + eh*8 + gid);
                #pragma unroll
                for (int nt = 0; nt < 8; nt++) {
                    int col = n0 + wc + nt*8 + 2*t4;
                    if (col + 1 < N) {
                        float2 v;
                        v.x = acc[mt][nt][eh*2+0] + bias[col];
                        v.y = acc[mt][nt][eh*2+1] + bias[col+1];
                        *(float2*)&C[row*(size_t)N + col] = v;
                    } else if (col < N) {
                        C[row*(size_t)N + col] = acc[mt][nt][eh*2] + bias[col];
                    }
                }
            }
    } else {
        float* sp = (float*)sm;
        int cg = wid >> 2;
        #pragma unroll
        for (int mt = 0; mt < 2; mt++)
            #pragma unroll
            for (int eh = 0; eh < 2; eh++) {
                int rloc = wr + mt*16 + eh*8 + gid;
                size_t row = (size_t)(m0 + rloc);
                float p = 0.f;
                #pragma unroll
                for (int nt = 0; nt < 8; nt++) {
                    int col = n0 + wc + nt*8 + 2*t4;
                    if (col + 1 < N) {
                        float2 v;
                        v.x = expf(acc[mt][nt][eh*2+0] + bias[col]);
                        v.y = expf(acc[mt][nt][eh*2+1] + bias[col+1]);
                        *(float2*)&C[row*(size_t)N + col] = v;
                        p += v.x + v.y;
                    } else if (col < N) {
                        float v = expf(acc[mt][nt][eh*2] + bias[col]);
                        C[row*(size_t)N + col] = v;
                        p += v;
                    }
                }
                p += __shfl_xor_sync(0xffffffffu, p, 1);
                p += __shfl_xor_sync(0xffffffffu, p, 2);
                if (t4 == 0) sp[rloc*2 + cg] = p;
            }
        __syncthreads();
        if (tid < 128)
            psum[(size_t)(m0 + tid)*NPX + blockIdx.x] = sp[tid*2] + sp[tid*2+1];
    }
}

// ---------- fused wh_app GEMM + energy: tile 64x256, 2-stage ----------
#define FK_STAGE 51200
#define FK_FLT   102400
#define FK_SMEM  107776
__global__ void __launch_bounds__(256) fk_whenergy(const float* __restrict__ A,
        const __nv_bfloat16* __restrict__ Wh, const __nv_bfloat16* __restrict__ Wl,
        const float* __restrict__ coverage,
        const float* __restrict__ awc, const float* __restrict__ av) {
    extern __shared__ __align__(16) char sm[];
    uint32_t sb = smem_u32(sm);
    float* swsA = (float*)(sm + FK_FLT);
    float* swsB = (float*)(sm + FK_FLT + 1024);
    float* sawc = (float*)(sm + FK_FLT + 2048);
    float* sav  = (float*)(sm + FK_FLT + 3072);
    float* scov = (float*)(sm + FK_FLT + 4096);
    float* sred = (float*)(sm + FK_FLT + 4352);

    int tid = threadIdx.x, wid = tid >> 5, lane = tid & 31;
    int m0 = blockIdx.x * 64;
    int b0 = m0 / S;
    int b1 = (b0 + 1 < B) ? b0 + 1 : b0;
    int bswitch = (b0 + 1) * S - m0;
    int wr = (wid & 1) * 32, wc = (wid >> 1) * 64;
    int lr = lane & 7, sect = lane >> 3;
    uint32_t aoff = (uint32_t)((wr + (sect & 1)*8 + lr)*80 + (sect >> 1)*16);
    uint32_t boff = (uint32_t)((wc + (sect >> 1)*8 + lr)*80 + (sect & 1)*16);

    swsA[tid] = g_wsapp[b0*H + tid];
    swsB[tid] = g_wsapp[b1*H + tid];
    sawc[tid] = awc[tid];
    sav[tid]  = av[tid];
    if (tid < 64) scov[tid] = coverage[(size_t)m0 + tid];

    const char* wHs = (const char*)(Wh + (size_t)tid*E);
    const char* wLs = (const char*)(Wl + (size_t)tid*E);
    uint32_t wdoff = (uint32_t)(tid*80);
    int ar = tid >> 2, akb = (tid & 3) * 8;
    const float* aSrc = A + (size_t)(m0 + ar)*E + akb;

    float acc[2][8][4];
    #pragma unroll
    for (int i = 0; i < 2; i++)
        #pragma unroll
        for (int j = 0; j < 8; j++)
            #pragma unroll
            for (int e = 0; e < 4; e++) acc[i][j][e] = 0.f;

    #pragma unroll
    for (int i = 0; i < 4; i++) {
        cpa(sb + wdoff + i*16,         wHs + i*16);
        cpa(sb + 20480 + wdoff + i*16, wLs + i*16);
    }
    CP_COMMIT();
    float4 aN0 = *(const float4*)(aSrc);
    float4 aN1 = *(const float4*)(aSrc + 4);

    for (int c = 0; c < E/32; c++) {
        uint32_t st = sb + (uint32_t)((c & 1) * FK_STAGE);
        char* stc = sm + (c & 1) * FK_STAGE;
        st_hilo(stc + 40960, stc + 46080, ar, akb,     aN0);
        st_hilo(stc + 40960, stc + 46080, ar, akb + 4, aN1);
        if (c + 1 < E/32) {
            uint32_t st2 = sb + (uint32_t)(((c+1) & 1) * FK_STAGE);
            int ko = (c + 1) * 64;
            #pragma unroll
            for (int i = 0; i < 4; i++) {
                cpa(st2 + wdoff + i*16,         wHs + ko + i*16);
                cpa(st2 + 20480 + wdoff + i*16, wLs + ko + i*16);
            }
            CP_COMMIT();
            aN0 = *(const float4*)(aSrc + (c+1)*32);
            aN1 = *(const float4*)(aSrc + (c+1)*32 + 4);
            CP_WAIT1();
        } else CP_WAIT0();
        __syncthreads();
        #pragma unroll
        for (int ks = 0; ks < 64; ks += 32)
            mma_step(acc, st + 40960 + aoff + ks, st + 46080 + aoff + ks,
                          st + boff + ks,         st + 20480 + boff + ks);
        __syncthreads();
    }

    int gid = lane >> 2, t4 = lane & 3;
    #pragma unroll
    for (int mt = 0; mt < 2; mt++)
        #pragma unroll
        for (int eh = 0; eh < 2; eh++) {
            int row = wr + mt*16 + eh*8 + gid;
            float c = scov[row];
            const float* sws = (row < bswitch) ? swsA : swsB;
            float p = 0.f;
            #pragma unroll
            for (int nt = 0; nt < 8; nt++)
                #pragma unroll
                for (int e2 = 0; e2 < 2; e2++) {
                    int h = wc + nt*8 + 2*t4 + e2;
                    float x = acc[mt][nt][eh*2 + e2] + sws[h] + c * sawc[h];
                    p += tanhf(x) * sav[h];
                }
            p += __shfl_xor_sync(0xffffffffu, p, 1);
            p += __shfl_xor_sync(0xffffffffu, p, 2);
            if (t4 == 0) sred[row*4 + (wid >> 1)] = p;
        }
    __syncthreads();
    if (tid < 64)
        g_energy[(size_t)m0 + tid] = sred[tid*4] + sred[tid*4+1] + sred[tid*4+2] + sred[tid*4+3];
}

// ---------- LSTM + p_gen ----------
__global__ void k_lstm(const float* __restrict__ c0, const float* __restrict__ ws,
                       float* __restrict__ out) {
    int b = blockIdx.x, h = threadIdx.x;
    __shared__ float red[32];
    const float* g = g_gates + (size_t)b*G4;
    float ig = sigmoidf_(g[h]);
    float fg = sigmoidf_(g[H + h]);
    float gg = tanhf(g[2*H + h]);
    float og = sigmoidf_(g[3*H + h]);
    float c  = fg * c0[b*H + h] + ig * gg;
    float ht = og * tanhf(c);
    out[OUT_CT + (size_t)b*H + h] = c;
    out[OUT_HT + (size_t)b*H + h] = ht;
    split2(ht, &g_htH[b*H + h], &g_htL[b*H + h]);
    float hw = blk_sum(ht * ws[h], red);
    if (h == 0)
        g_pgen[b] = sigmoidf_(g_cwp[b] + g_cwp[B+b] + g_cwp[2*B+b] + g_cwp[3*B+b] + hw + g_exw[b]);
}

// ---------- vocab softmax: reduce partials, scale ----------
__global__ void k_rowsum() {
    int b = blockIdx.x, tid = threadIdx.x;
    __shared__ float red[32];
    float s = 0.f;
    for (int i = tid; i < NPX; i += 512) s += g_psum[(size_t)b*NPX + i];
    float t = blk_sum(s, red);
    if (tid == 0) g_rowinv[b] = 1.f / t;
}
__global__ void k_norm(float* __restrict__ out) {
    int b = blockIdx.y;
    int i = (blockIdx.x*blockDim.x + threadIdx.x) * 4;
    if (i < V) {
        float4* p = (float4*)(out + (size_t)b*V + i);
        float4 v = *p;
        float sc = g_pgen[b] * g_rowinv[b];
        v.x *= sc; v.y *= sc; v.z *= sc; v.w *= sc;
        *p = v;
    }
}

// ---------- attention softmax + coverage + loss ----------
__global__ void k_attnA(const float* __restrict__ coverage, float* __restrict__ out) {
    int b = blockIdx.x, tid = threadIdx.x;
    __shared__ float red[32];
    float e = (tid < S) ? g_energy[b*S + tid] : -1e30f;
    float m = blk_max(e, red);
    float ex = (tid < S) ? expf(e - m) : 0.f;
    float sum = blk_sum(ex, red);
    float part = 0.f;
    if (tid < S) {
        float a = ex / sum;
        out[OUT_ATTN + (size_t)b*S + tid] = a;
        float c = coverage[(size_t)b*S + tid];
        out[OUT_COV + (size_t)b*S + tid] = c + a;
        part = fminf(a, c);
    }
    float ps = blk_sum(part, red);
    if (tid == 0) g_covpart[b] = ps;
}
__global__ void k_loss(float* __restrict__ out) {
    __shared__ float red[32];
    float s = blk_sum(g_covpart[threadIdx.x], red);
    if (threadIdx.x == 0) out[OUT_LOSS] = s;
}
// ---------- scatter (last-s-wins), after k_norm ----------
__global__ void k_scat(const int* __restrict__ enc_inputs, float* __restrict__ out) {
    int b = blockIdx.x, tid = threadIdx.x;
    __shared__ int   sidx[S];
    __shared__ float sat[S];
    if (tid < S) {
        sidx[tid] = enc_inputs[(size_t)b*S + tid];
        sat[tid]  = out[OUT_ATTN + (size_t)b*S + tid];
    }
    __syncthreads();
    if (tid < S) {
        int v = sidx[tid];
        bool win = true;
        for (int s2 = tid + 1; s2 < S; s2++)
            if (sidx[s2] == v) { win = false; break; }
        if (win) out[(size_t)b*V + v] += (1.f - g_pgen[b]) * sat[tid];
    }
}

// ---------- host ----------
extern "C" void kernel_launch(void* const* d_in, const int* in_sizes, int n_in,
                              void* d_out, int out_size) {
    const float* coverage   = (const float*)d_in[0];
    const float* enc_out    = (const float*)d_in[1];
    const float* h0         = (const float*)d_in[2];
    const float* c0         = (const float*)d_in[3];
    const float* attn       = (const float*)d_in[4];
    const int*   dec_input  = (const int*)d_in[5];
    const int*   enc_inputs = (const int*)d_in[6];
    const float* emb_table  = (const float*)d_in[7];
    const float* W_ih       = (const float*)d_in[8];
    const float* W_hh       = (const float*)d_in[9];
    const float* b_ih       = (const float*)d_in[10];
    const float* b_hh       = (const float*)d_in[11];
    const float* awh_W      = (const float*)d_in[12];
    const float* awh_b      = (const float*)d_in[13];
    const float* aws_W      = (const float*)d_in[14];
    const float* aws_b      = (const float*)d_in[15];
    const float* awc        = (const float*)d_in[16];
    const float* av         = (const float*)d_in[17];
    const float* wh         = (const float*)d_in[18];
    const float* ws         = (const float*)d_in[19];
    const float* wx         = (const float*)d_in[20];
    const float* v_W        = (const float*)d_in[21];
    const float* v_b        = (const float*)d_in[22];
    float* out = (float*)d_out;

    float *p_bcat, *p_gates, *p_wsapp, *p_bias2, *p_psum;
    __nv_bfloat16 *p_WcatH, *p_WcatL, *p_xcatH, *p_xcatL, *p_awhH, *p_awhL;
    __nv_bfloat16 *p_awsH, *p_awsL, *p_vWH, *p_vWL, *p_htH, *p_htL;
    cudaGetSymbolAddress((void**)&p_bcat,  g_bcat);
    cudaGetSymbolAddress((void**)&p_gates, g_gates);
    cudaGetSymbolAddress((void**)&p_wsapp, g_wsapp);
    cudaGetSymbolAddress((void**)&p_bias2, g_bias2);
    cudaGetSymbolAddress((void**)&p_psum,  g_psum);
    cudaGetSymbolAddress((void**)&p_WcatH, g_WcatH);
    cudaGetSymbolAddress((void**)&p_WcatL, g_WcatL);
    cudaGetSymbolAddress((void**)&p_xcatH, g_xcatH);
    cudaGetSymbolAddress((void**)&p_xcatL, g_xcatL);
    cudaGetSymbolAddress((void**)&p_awhH,  g_awhH);
    cudaGetSymbolAddress((void**)&p_awhL,  g_awhL);
    cudaGetSymbolAddress((void**)&p_awsH,  g_awsH);
    cudaGetSymbolAddress((void**)&p_awsL,  g_awsL);
    cudaGetSymbolAddress((void**)&p_vWH,   g_vWH);
    cudaGetSymbolAddress((void**)&p_vWL,   g_vWL);
    cudaGetSymbolAddress((void**)&p_htH,   g_htH);
    cudaGetSymbolAddress((void**)&p_htL,   g_htL);

    cudaFuncSetAttribute(fk_whenergy, cudaFuncAttributeMaxDynamicSharedMemorySize, FK_SMEM);
    cudaFuncSetAttribute(hgemm,       cudaFuncAttributeMaxDynamicSharedMemorySize, HG_SMEM);

    static cudaStream_t s2 = nullptr;
    static cudaEvent_t evA = nullptr, evB = nullptr, evL = nullptr, evD = nullptr;
    if (s2 == nullptr) {
        cudaStreamCreateWithFlags(&s2, cudaStreamNonBlocking);
        cudaEventCreateWithFlags(&evA, cudaEventDisableTiming);
        cudaEventCreateWithFlags(&evB, cudaEventDisableTiming);
        cudaEventCreateWithFlags(&evL, cudaEventDisableTiming);
        cudaEventCreateWithFlags(&evD, cudaEventDisableTiming);
    }

    // fork: weight prep on s2, hidden under context on main
    cudaEventRecord(evA, 0);
    cudaStreamWaitEvent(s2, evA, 0);
    k_packw<<<(G4*KX + 255)/256, 256, 0, s2>>>(W_ih, W_hh, b_ih, b_hh, aws_b, awh_b);
    k_cvt2<<<((H*E + H*H)/4 + 255)/256, 256, 0, s2>>>(awh_W, p_awhH, p_awhL, H*E,
                                                      aws_W, p_awsH, p_awsL, H*H);
    k_cvt<<<(V*H/4 + 255)/256, 256, 0, s2>>>(v_W, p_vWH, p_vWL, V*H);
    cudaEventRecord(evB, s2);

    // main: context -> packx -> (join weights) -> gates -> lstm
    k_context<<<dim3(B, 4), 256>>>(attn, enc_out, dec_input, emb_table, wh, wx);
    k_packx<<<(B*KX + 255)/256, 256>>>(h0);
    cudaStreamWaitEvent(0, evB, 0);
    hgemm<<<dim3(G4/128, B/128), 256, HG_SMEM>>>(p_xcatH, p_xcatL, p_WcatH, p_WcatL, p_bcat, p_gates, G4, KX, nullptr);
    k_lstm<<<B, 256>>>(c0, ws, out);
    cudaEventRecord(evL, 0);   // h_t + pgen ready

    // s2: logits chain (independent of fk) — exp-GEMM -> rowsum -> norm
    cudaStreamWaitEvent(s2, evL, 0);
    hgemm<<<dim3(NPX, B/128), 256, HG_SMEM, s2>>>(p_htH, p_htL, p_vWH, p_vWL, v_b, out, V, H, p_psum);
    k_rowsum<<<B, 512, 0, s2>>>();
    k_norm<<<dim3((V/4 + 255)/256, B), 256, 0, s2>>>(out);
    cudaEventRecord(evD, s2);

    // main: wsapp -> fk energy -> attn softmax/coverage/loss
    hgemm<<<dim3(H/128, B/128), 256, HG_SMEM>>>(p_htH, p_htL, p_awsH, p_awsL, p_bias2, p_wsapp, H, H, nullptr);
    fk_whenergy<<<(B*S)/64, 256, FK_SMEM>>>(enc_out, p_awhH, p_awhL, coverage, awc, av);
    k_attnA<<<B, 512>>>(coverage, out);
    k_loss<<<1, B>>>(out);

    // join: vocab block normalized + attn written -> scatter
    cudaStreamWaitEvent(0, evD, 0);
    k_scat<<<B, 512>>>(enc_inputs, out);
}